// round 12
// baseline (speedup 1.0000x reference)
#include <cuda_runtime.h>
#include <cuda_bf16.h>
#include <cuda_fp16.h>
#include <cstdint>
#include <cstddef>

#define BATCH 2
#define SEQ 2048
#define SPAD 2050
#define DMODEL 1024
#define NHEAD 16
#define PADROWS (BATCH * SPAD)

// ===========================================================================
// Scratch
// ===========================================================================
__device__ __nv_bfloat16 g_hi[3 * PADROWS * DMODEL];
__device__ __nv_bfloat16 g_lo[3 * PADROWS * DMODEL];
__device__ __nv_bfloat16 g_qkvh[2 * PADROWS * DMODEL];  // q,k hi
__device__ __nv_bfloat16 g_qkvl[2 * PADROWS * DMODEL];  // q,k lo
__device__ __half        g_vf[PADROWS * DMODEL];        // v single fp16
__device__ __nv_bfloat16 g_aoh[PADROWS * DMODEL];
__device__ __nv_bfloat16 g_aol[PADROWS * DMODEL];
__device__ __nv_bfloat16 g_Wqc[DMODEL * 6144];   // {Whi x3 taps, Wlo x3 taps}
__device__ __nv_bfloat16 g_Wkc[DMODEL * 6144];
__device__ __nv_bfloat16 g_Wvc[DMODEL * 2048];   // {Whi, Wlo}
__device__ __nv_bfloat16 g_Wcc[DMODEL * 2048];
__device__ float g_bq[DMODEL], g_bk[DMODEL], g_bv[DMODEL], g_bc[DMODEL];

// ===========================================================================
// PTX helpers (sm_80-era only; valid on compute_103)
// ===========================================================================
__device__ __forceinline__ uint32_t smem_to_u32(const void* p) {
    uint32_t a;
    asm("{ .reg .u64 t; cvta.to.shared.u64 t, %1; cvt.u32.u64 %0, t; }" : "=r"(a) : "l"(p));
    return a;
}
__device__ __forceinline__ void cp16(uint32_t dst, const void* src) {
    asm volatile("cp.async.cg.shared.global [%0], [%1], 16;" :: "r"(dst), "l"(src));
}
__device__ __forceinline__ void ldsm_x4(uint32_t* r, uint32_t addr) {
    asm volatile("ldmatrix.sync.aligned.m8n8.x4.shared.b16 {%0,%1,%2,%3}, [%4];"
        : "=r"(r[0]), "=r"(r[1]), "=r"(r[2]), "=r"(r[3]) : "r"(addr));
}
__device__ __forceinline__ void ldsm_x4_t(uint32_t* r, uint32_t addr) {
    asm volatile("ldmatrix.sync.aligned.m8n8.x4.trans.shared.b16 {%0,%1,%2,%3}, [%4];"
        : "=r"(r[0]), "=r"(r[1]), "=r"(r[2]), "=r"(r[3]) : "r"(addr));
}
__device__ __forceinline__ void mma_bf16(float* d, const uint32_t* a, const uint32_t* b) {
    asm volatile(
        "mma.sync.aligned.m16n8k16.row.col.f32.bf16.bf16.f32 "
        "{%0,%1,%2,%3}, {%4,%5,%6,%7}, {%8,%9}, {%0,%1,%2,%3};"
        : "+f"(d[0]), "+f"(d[1]), "+f"(d[2]), "+f"(d[3])
        : "r"(a[0]), "r"(a[1]), "r"(a[2]), "r"(a[3]), "r"(b[0]), "r"(b[1]));
}
__device__ __forceinline__ void mma_f16(float* d, const uint32_t* a, const uint32_t* b) {
    asm volatile(
        "mma.sync.aligned.m16n8k16.row.col.f32.f16.f16.f32 "
        "{%0,%1,%2,%3}, {%4,%5,%6,%7}, {%8,%9}, {%0,%1,%2,%3};"
        : "+f"(d[0]), "+f"(d[1]), "+f"(d[2]), "+f"(d[3])
        : "r"(a[0]), "r"(a[1]), "r"(a[2]), "r"(a[3]), "r"(b[0]), "r"(b[1]));
}
__device__ __forceinline__ uint32_t pack_bf16(float lo, float hi) {
    uint32_t r; asm("cvt.rn.bf16x2.f32 %0, %1, %2;" : "=r"(r) : "f"(hi), "f"(lo)); return r;
}
__device__ __forceinline__ uint32_t pack_f16(float lo, float hi) {
    uint32_t r; asm("cvt.rn.f16x2.f32 %0, %1, %2;" : "=r"(r) : "f"(hi), "f"(lo)); return r;
}
__device__ __forceinline__ float f_low(uint32_t r)  { return __uint_as_float(r << 16); }
__device__ __forceinline__ float f_high(uint32_t r) { return __uint_as_float(r & 0xffff0000u); }
__device__ __forceinline__ float ex2f(float x) {
    float r; asm("ex2.approx.f32 %0, %1;" : "=f"(r) : "f"(x)); return r;
}
__device__ __forceinline__ void split_pair(float v0, float v1, uint32_t& h2, uint32_t& l2) {
    h2 = pack_bf16(v0, v1);
    l2 = pack_bf16(v0 - f_low(h2), v1 - f_high(h2));
}

// ===========================================================================
// Fused prep: split all 3 activations. grid (1, SPAD, 6): z = b + 2*t
// ===========================================================================
struct SArgs { const float* X[3]; __nv_bfloat16* hi[3]; __nv_bfloat16* lo[3]; };

__global__ void split_act_all(SArgs sa) {
    int z = blockIdx.z;
    int t = z >> 1, b = z & 1;
    int y = blockIdx.y;
    int c = threadIdx.x << 2;
    float4 v = make_float4(0.f, 0.f, 0.f, 0.f);
    if (y >= 1 && y <= SEQ)
        v = *(const float4*)&sa.X[t][(((size_t)b * SEQ + (y - 1)) << 10) + c];
    uint32_t h0, l0, h1, l1;
    split_pair(v.x, v.y, h0, l0);
    split_pair(v.z, v.w, h1, l1);
    size_t o = (((size_t)b * SPAD + y) << 10) + c;
    *(uint2*)&sa.hi[t][o] = make_uint2(h0, h1);
    *(uint2*)&sa.lo[t][o] = make_uint2(l0, l1);
}

// ===========================================================================
// Fused prep: all 4 weight transforms. grid (1024, 4)
// ===========================================================================
struct WArgs {
    const float* w[4]; const float* b[4];
    __nv_bfloat16* out[4]; float* bP[4];
    int KS[4]; int perm[4];
};

__global__ void transform_w_all(WArgs wa) {
    int ws = blockIdx.y;
    int c = blockIdx.x;
    int i = threadIdx.x << 2;
    int KS = wa.KS[ws];
    int o = wa.perm[ws] ? ((c & 63) * 16 + (c >> 6)) : c;
    const float* src = wa.w[ws] + ((size_t)o * 1024 + i) * KS;
    __nv_bfloat16* Wcat = wa.out[ws];
    const int W2 = (KS << 1) << 10;
    for (int tap = 0; tap < KS; tap++) {
        float v0 = src[0 * KS + tap], v1 = src[1 * KS + tap];
        float v2 = src[2 * KS + tap], v3 = src[3 * KS + tap];
        uint32_t h0, l0, h1, l1;
        split_pair(v0, v1, h0, l0);
        split_pair(v2, v3, h1, l1);
        *(uint2*)&Wcat[(size_t)c * W2 + ((size_t)tap << 10) + i] = make_uint2(h0, h1);
        *(uint2*)&Wcat[(size_t)c * W2 + ((size_t)(KS + tap) << 10) + i] = make_uint2(l0, l1);
    }
    if (threadIdx.x == 0) wa.bP[ws][c] = wa.b[ws][o];
}

// ===========================================================================
// HMMA split-bf16 conv-GEMM v5: BM=128, BN=256, warp tile 32x128.
// 8 warps (4m x 2n). mma:ldsm ratio 5.3 (was 4.0). 1 CTA/SM (148.6KB smem).
// Same term schedule: per chunk, 2*KS segments s; s<KS: Whi tap s (A hi+lo),
// s>=KS: Wlo tap s-KS (A hi only).
// ===========================================================================
#define G4_AMAT 18720                  // 130 rows * 144 B
#define G4_ABUF (2 * G4_AMAT)          // hi+lo = 37440
#define G4_AREG (2 * G4_ABUF)          // double buffer = 74880
#define G5_BTILE 36864                 // 256 n-rows * 144 B
#define GEMM_SMEM (G4_AREG + 2 * G5_BTILE)   // 148608

struct GArgs {
    const __nv_bfloat16* Ah[3]; const __nv_bfloat16* Al[3];
    const __nv_bfloat16* Bw[3]; const float* bias[3];
    void* Ch[3]; __nv_bfloat16* Cl[3];
    float* Cf;
    int KS[3];
    int outMode[3];
};

__global__ void __launch_bounds__(256, 1) gemm_hmma_kernel(GArgs ga)
{
    extern __shared__ __align__(128) char smem[];
    const uint32_t sb = smem_to_u32(smem);
    const int tid = threadIdx.x, wid = tid >> 5, lane = tid & 31;
    const int z = blockIdx.z;
    const __nv_bfloat16* __restrict__ Ahi = ga.Ah[z];
    const __nv_bfloat16* __restrict__ Alo = ga.Al[z];
    const __nv_bfloat16* __restrict__ Bw  = ga.Bw[z];
    const float* __restrict__ bP = ga.bias[z];
    const int KS = ga.KS[z];

    const int row0 = blockIdx.y << 7;            // 128 rows
    const int col0 = blockIdx.x << 8;            // 256 cols
    const int bb = row0 >> 11;
    const size_t base = (size_t)bb * SPAD + (row0 & 2047);
    const int NSEG = KS << 1;
    const int Kp = NSEG << 10;
    const int J = NSEG << 4;
    const int tapAdd = (KS == 1) ? 1 : 0;
    const int wm = (wid >> 1) << 5;              // 0,32,64,96
    const int wn = (wid & 1) << 7;               // 0,128

    auto load_A = [&](int ch) {
        uint32_t dst = sb + (uint32_t)(ch & 1) * G4_ABUF;
        int c0 = ch << 6;
#pragma unroll
        for (int l = 0; l < 9; l++) {
            int idx = tid + (l << 8);
            if (idx < 2080) {
                int mat = 0;
                if (idx >= 1040) { idx -= 1040; mat = 1; }
                int r = idx >> 3, jc = idx & 7;
                const __nv_bfloat16* src = (mat ? Alo : Ahi)
                    + (((base + r) << 10) + c0 + (jc << 3));
                cp16(dst + (uint32_t)(mat * G4_AMAT + r * 144 + (jc << 4)), src);
            }
        }
    };
    auto load_B = [&](int j, int s, int ch) {
        uint32_t dst = sb + G4_AREG + (uint32_t)(j & 1) * G5_BTILE;
        size_t k0 = ((size_t)s << 10) + (ch << 6);
#pragma unroll
        for (int l = 0; l < 8; l++) {
            int idx = tid + (l << 8);                 // 0..2047
            int r = idx >> 3, jc = idx & 7;           // r: 0..255 n-rows
            cp16(dst + (uint32_t)(r * 144 + (jc << 4)),
                 Bw + (size_t)(col0 + r) * Kp + k0 + (jc << 3));
        }
    };

    float acc[2][16][4];
#pragma unroll
    for (int mt = 0; mt < 2; mt++)
#pragma unroll
        for (int nt = 0; nt < 16; nt++)
#pragma unroll
            for (int e = 0; e < 4; e++) acc[mt][nt][e] = 0.f;

    load_A(0);
    load_B(0, 0, 0);
    asm volatile("cp.async.commit_group;");

    int s = 0, ch = 0;
    for (int j = 0; j < J; j++) {
        if (s == 0 && ch + 1 < 16) load_A(ch + 1);
        if (j + 1 < J) {
            int s2 = s + 1, ch2 = ch;
            if (s2 == NSEG) { s2 = 0; ch2++; }
            load_B(j + 1, s2, ch2);
            asm volatile("cp.async.commit_group;");
            asm volatile("cp.async.wait_group 1;");
        } else {
            asm volatile("cp.async.commit_group;");
            asm volatile("cp.async.wait_group 0;");
        }
        __syncthreads();

        const int tap = (s < KS ? s : s - KS) + tapAdd;
        const bool doLo = (s < KS);
        const uint32_t AsmHi = sb + (uint32_t)(ch & 1) * G4_ABUF;
        const uint32_t AsmLo = AsmHi + G4_AMAT;
        const uint32_t Bsm = sb + G4_AREG + (uint32_t)(j & 1) * G5_BTILE;

#pragma unroll
        for (int kk = 0; kk < 64; kk += 16) {
            uint32_t b[8][4], a[2][4];
#pragma unroll
            for (int g = 0; g < 8; g++) {
                int nrow = wn + g * 16 + (lane & 7) + ((lane >> 4) << 3);
                ldsm_x4(b[g], Bsm + (uint32_t)(nrow * 144 + (kk + (((lane >> 3) & 1) << 3)) * 2));
            }
#pragma unroll
            for (int mt = 0; mt < 2; mt++)
                ldsm_x4(a[mt], AsmHi + (uint32_t)((wm + tap + mt * 16 + (lane & 15)) * 144
                        + ((lane >> 4) << 4) + kk * 2));
#pragma unroll
            for (int mt = 0; mt < 2; mt++)
#pragma unroll
                for (int g = 0; g < 8; g++) {
                    mma_bf16(acc[mt][2 * g + 0], a[mt], &b[g][0]);
                    mma_bf16(acc[mt][2 * g + 1], a[mt], &b[g][2]);
                }
            if (doLo) {
#pragma unroll
                for (int mt = 0; mt < 2; mt++)
                    ldsm_x4(a[mt], AsmLo + (uint32_t)((wm + tap + mt * 16 + (lane & 15)) * 144
                            + ((lane >> 4) << 4) + kk * 2));
#pragma unroll
                for (int mt = 0; mt < 2; mt++)
#pragma unroll
                    for (int g = 0; g < 8; g++) {
                        mma_bf16(acc[mt][2 * g + 0], a[mt], &b[g][0]);
                        mma_bf16(acc[mt][2 * g + 1], a[mt], &b[g][2]);
                    }
            }
        }
        __syncthreads();
        if (++s == NSEG) { s = 0; ch++; }
    }

    const int om = ga.outMode[z];
    if (om == 0) {
        __nv_bfloat16* __restrict__ Chi = (__nv_bfloat16*)ga.Ch[z];
        __nv_bfloat16* __restrict__ Clo = ga.Cl[z];
        const int prow0 = bb * SPAD + (row0 & 2047) + 1;
#pragma unroll
        for (int mt = 0; mt < 2; mt++) {
            int rl = wm + mt * 16 + (lane >> 2);
#pragma unroll
            for (int nt = 0; nt < 16; nt++) {
                int c = col0 + wn + nt * 8 + ((lane & 3) << 1);
                float2 bv = *(const float2*)&bP[c];
                uint32_t h2, l2;
                split_pair(acc[mt][nt][0] + bv.x, acc[mt][nt][1] + bv.y, h2, l2);
                size_t o0 = ((size_t)(prow0 + rl) << 10) + c;
                *(uint32_t*)&Chi[o0] = h2;
                *(uint32_t*)&Clo[o0] = l2;
                split_pair(acc[mt][nt][2] + bv.x, acc[mt][nt][3] + bv.y, h2, l2);
                size_t o1 = ((size_t)(prow0 + rl + 8) << 10) + c;
                *(uint32_t*)&Chi[o1] = h2;
                *(uint32_t*)&Clo[o1] = l2;
            }
        }
    } else if (om == 1) {
        __half* __restrict__ Cv = (__half*)ga.Ch[z];
        const int prow0 = bb * SPAD + (row0 & 2047) + 1;
#pragma unroll
        for (int mt = 0; mt < 2; mt++) {
            int rl = wm + mt * 16 + (lane >> 2);
#pragma unroll
            for (int nt = 0; nt < 16; nt++) {
                int c = col0 + wn + nt * 8 + ((lane & 3) << 1);
                float2 bv = *(const float2*)&bP[c];
                uint32_t p0 = pack_f16(acc[mt][nt][0] + bv.x, acc[mt][nt][1] + bv.y);
                uint32_t p1 = pack_f16(acc[mt][nt][2] + bv.x, acc[mt][nt][3] + bv.y);
                *(uint32_t*)&Cv[((size_t)(prow0 + rl) << 10) + c] = p0;
                *(uint32_t*)&Cv[((size_t)(prow0 + rl + 8) << 10) + c] = p1;
            }
        }
    } else {
        float* __restrict__ Cf = ga.Cf;
#pragma unroll
        for (int mt = 0; mt < 2; mt++) {
            int r = row0 + wm + mt * 16 + (lane >> 2);
#pragma unroll
            for (int nt = 0; nt < 16; nt++) {
                int c = col0 + wn + nt * 8 + ((lane & 3) << 1);
                float2 bv = *(const float2*)&bP[c];
                *(float2*)&Cf[(size_t)r * 1024 + c] =
                    make_float2(acc[mt][nt][0] + bv.x, acc[mt][nt][1] + bv.y);
                *(float2*)&Cf[(size_t)(r + 8) * 1024 + c] =
                    make_float2(acc[mt][nt][2] + bv.x, acc[mt][nt][3] + bv.y);
            }
        }
    }
}

// ===========================================================================
// HMMA flash attention v3 (exact round-10 version — 197us, passing)
// ===========================================================================
#define AT_QREG 18432
#define AT_KVBUF 27648
#define AT_SMEM (AT_QREG + 2 * AT_KVBUF + 1024)   // 74752

__global__ void __launch_bounds__(256, 2) attn_hmma_kernel(
    const __nv_bfloat16* __restrict__ Qh, const __nv_bfloat16* __restrict__ Ql,
    const __nv_bfloat16* __restrict__ Kh, const __nv_bfloat16* __restrict__ Kl,
    const __half* __restrict__ Vf,
    __nv_bfloat16* __restrict__ Oh, __nv_bfloat16* __restrict__ Ol)
{
    extern __shared__ __align__(128) char smem[];
    const uint32_t sb = smem_to_u32(smem);
    const uint32_t sKV = sb + AT_QREG;
    float* rs2 = (float*)(smem + AT_QREG + 2 * AT_KVBUF);
    float* outcmb = (float*)(smem + AT_QREG);

    const int tid = threadIdx.x, wid = tid >> 5, lane = tid & 31;
    const int wm = (wid >> 1) << 4;
    const int wnk = (wid & 1) << 5;
    const int q0 = blockIdx.x << 6;
    const int h = blockIdx.y, b = blockIdx.z;
    const size_t hoff = (size_t)h * 64;
    const size_t rowbase = (size_t)b * SPAD + 1;

#pragma unroll
    for (int l = 0; l < 4; l++) {
        int mat = l >> 1;
        int r = (tid >> 3) + ((l & 1) << 5);
        int j = tid & 7;
        const __nv_bfloat16* src = (mat ? Ql : Qh) + (((rowbase + q0 + r) << 10) + hoff + (j << 3));
        cp16(sb + (uint32_t)(mat * 9216 + r * 144 + j * 16), src);
    }
    asm volatile("cp.async.commit_group;");

    auto loadKV = [&](int c) {
        uint32_t dstb = sKV + (uint32_t)(c & 1) * AT_KVBUF;
        size_t krow = rowbase + ((size_t)c << 6);
#pragma unroll
        for (int l = 0; l < 6; l++) {
            int mat = l >> 1;                     // 0:Kh 1:Kl 2:Vf
            int r = (tid >> 3) + ((l & 1) << 5);
            int j = tid & 7;
            const void* src;
            if (mat == 0)      src = Kh + (((krow + r) << 10) + hoff + (j << 3));
            else if (mat == 1) src = Kl + (((krow + r) << 10) + hoff + (j << 3));
            else               src = Vf + (((krow + r) << 10) + hoff + (j << 3));
            cp16(dstb + (uint32_t)(mat * 9216 + r * 144 + j * 16), src);
        }
    };
    loadKV(0);
    asm volatile("cp.async.commit_group;");

    float outacc[8][4];
    float rs[2] = {0.f, 0.f};
#pragma unroll
    for (int nt = 0; nt < 8; nt++)
#pragma unroll
        for (int e = 0; e < 4; e++) outacc[nt][e] = 0.f;

    const float CEXP = 1.4426950408889634f * 0.125f;   // log2(e)/8
    const float EBIAS = 17.312340490667562f;           // 12*log2(e)

    for (int c = 0; c < 32; c++) {
        if (c + 1 < 32) {
            loadKV(c + 1);
            asm volatile("cp.async.commit_group;");
            asm volatile("cp.async.wait_group 1;");
        } else {
            asm volatile("cp.async.wait_group 0;");
        }
        __syncthreads();
        uint32_t bufb = sKV + (uint32_t)(c & 1) * AT_KVBUF;

        float sc[4][4];
#pragma unroll
        for (int nt = 0; nt < 4; nt++)
#pragma unroll
            for (int e = 0; e < 4; e++) sc[nt][e] = 0.f;

#pragma unroll
        for (int ks = 0; ks < 4; ks++) {
            uint32_t ah[4], al[4], bh[2][4], bl[2][4];
            uint32_t qaddr = sb + (uint32_t)((wm + (lane & 15)) * 144
                             + ((lane >> 4) << 4) + ks * 32);
            ldsm_x4(ah, qaddr);
            ldsm_x4(al, qaddr + 9216);
#pragma unroll
            for (int g = 0; g < 2; g++) {
                int nrow = wnk + g * 16 + (lane & 7) + ((lane >> 4) << 3);
                uint32_t kaddr = bufb + (uint32_t)(nrow * 144 + ks * 32 + (((lane >> 3) & 1) << 4));
                ldsm_x4(bh[g], kaddr);
                ldsm_x4(bl[g], kaddr + 9216);
            }
#pragma unroll
            for (int g = 0; g < 2; g++) {
                mma_bf16(sc[2 * g + 0], ah, &bh[g][0]);
                mma_bf16(sc[2 * g + 1], ah, &bh[g][2]);
                mma_bf16(sc[2 * g + 0], ah, &bl[g][0]);
                mma_bf16(sc[2 * g + 1], ah, &bl[g][2]);
                mma_bf16(sc[2 * g + 0], al, &bh[g][0]);
                mma_bf16(sc[2 * g + 1], al, &bh[g][2]);
            }
        }

        uint32_t phi[2][4];
#pragma unroll
        for (int nt = 0; nt < 4; nt++)
#pragma unroll
            for (int e = 0; e < 4; e++) {
                float p = ex2f(sc[nt][e] * CEXP - EBIAS);
                sc[nt][e] = p;
                rs[e >> 1] += p;
            }
#pragma unroll
        for (int kt = 0; kt < 2; kt++) {
            phi[kt][0] = pack_f16(sc[2 * kt][0], sc[2 * kt][1]);
            phi[kt][1] = pack_f16(sc[2 * kt][2], sc[2 * kt][3]);
            phi[kt][2] = pack_f16(sc[2 * kt + 1][0], sc[2 * kt + 1][1]);
            phi[kt][3] = pack_f16(sc[2 * kt + 1][2], sc[2 * kt + 1][3]);
        }

#pragma unroll
        for (int kt = 0; kt < 2; kt++) {
            uint32_t vh[4][4];
#pragma unroll
            for (int g = 0; g < 4; g++) {
                int keyrow = wnk + kt * 16 + (lane & 7) + (((lane >> 3) & 1) << 3);
                uint32_t vaddr = bufb + 18432
                               + (uint32_t)(keyrow * 144 + g * 32 + ((lane >> 4) << 4));
                ldsm_x4_t(vh[g], vaddr);
            }
#pragma unroll
            for (int g = 0; g < 4; g++) {
                mma_f16(outacc[2 * g + 0], phi[kt], &vh[g][0]);
                mma_f16(outacc[2 * g + 1], phi[kt], &vh[g][2]);
            }
        }
        __syncthreads();
    }

#pragma unroll
    for (int hf = 0; hf < 2; hf++) {
        rs[hf] += __shfl_xor_sync(0xffffffffu, rs[hf], 1);
        rs[hf] += __shfl_xor_sync(0xffffffffu, rs[hf], 2);
    }
    if ((lane & 3) == 0) {
#pragma unroll
        for (int hf = 0; hf < 2; hf++)
            rs2[(wm + (lane >> 2) + hf * 8) * 2 + (wid & 1)] = rs[hf];
    }
    if (wid & 1) {
#pragma unroll
        for (int nt = 0; nt < 8; nt++)
#pragma unroll
            for (int e = 0; e < 4; e++) {
                int row = wm + (lane >> 2) + (e >> 1) * 8;
                int col = nt * 8 + ((lane & 3) << 1) + (e & 1);
                outcmb[row * 66 + col] = outacc[nt][e];
            }
    }
    __syncthreads();
    if (!(wid & 1)) {
        int r0 = wm + (lane >> 2);
#pragma unroll
        for (int hf = 0; hf < 2; hf++) {
            int row = r0 + hf * 8;
            float inv = 1.f / (rs2[row * 2] + rs2[row * 2 + 1]);
            size_t grow = ((rowbase + q0 + row) << 10) + hoff;
#pragma unroll
            for (int nt = 0; nt < 8; nt++) {
                int col = nt * 8 + ((lane & 3) << 1);
                float v0 = (outacc[nt][hf * 2 + 0] + outcmb[row * 66 + col]) * inv;
                float v1 = (outacc[nt][hf * 2 + 1] + outcmb[row * 66 + col + 1]) * inv;
                uint32_t h2, l2;
                split_pair(v0, v1, h2, l2);
                *(uint32_t*)&Oh[grow + col] = h2;
                *(uint32_t*)&Ol[grow + col] = l2;
            }
        }
    }
}

// ===========================================================================
// Launch
// ===========================================================================
extern "C" void kernel_launch(void* const* d_in, const int* in_sizes, int n_in,
                              void* d_out, int out_size) {
    const float* q    = (const float*)d_in[0];
    const float* k    = (const float*)d_in[1];
    const float* v    = (const float*)d_in[2];
    const float* wq_w = (const float*)d_in[3];
    const float* wq_b = (const float*)d_in[4];
    const float* wk_w = (const float*)d_in[5];
    const float* wk_b = (const float*)d_in[6];
    const float* wv_w = (const float*)d_in[7];
    const float* wv_b = (const float*)d_in[8];
    const float* wc_w = (const float*)d_in[9];
    const float* wc_b = (const float*)d_in[10];

    __nv_bfloat16 *pHi, *pLo, *pQKVh, *pQKVl, *pAOh, *pAOl, *pWq, *pWk, *pWv, *pWc;
    __half* pVf;
    float *pbq, *pbk, *pbv, *pbc;
    cudaGetSymbolAddress((void**)&pHi, g_hi);
    cudaGetSymbolAddress((void**)&pLo, g_lo);
    cudaGetSymbolAddress((void**)&pQKVh, g_qkvh);
    cudaGetSymbolAddress((void**)&pQKVl, g_qkvl);
    cudaGetSymbolAddress((void**)&pVf, g_vf);
    cudaGetSymbolAddress((void**)&pAOh, g_aoh);
    cudaGetSymbolAddress((void**)&pAOl, g_aol);
    cudaGetSymbolAddress((void**)&pWq, g_Wqc);
    cudaGetSymbolAddress((void**)&pWk, g_Wkc);
    cudaGetSymbolAddress((void**)&pWv, g_Wvc);
    cudaGetSymbolAddress((void**)&pWc, g_Wcc);
    cudaGetSymbolAddress((void**)&pbq, g_bq);
    cudaGetSymbolAddress((void**)&pbk, g_bk);
    cudaGetSymbolAddress((void**)&pbv, g_bv);
    cudaGetSymbolAddress((void**)&pbc, g_bc);

    const int TSLOT = PADROWS * DMODEL;

    cudaFuncSetAttribute(gemm_hmma_kernel, cudaFuncAttributeMaxDynamicSharedMemorySize, GEMM_SMEM);
    cudaFuncSetAttribute(attn_hmma_kernel, cudaFuncAttributeMaxDynamicSharedMemorySize, AT_SMEM);

    // 1) fused activation split
    SArgs sa;
    sa.X[0] = q; sa.X[1] = k; sa.X[2] = v;
    for (int t = 0; t < 3; t++) { sa.hi[t] = pHi + t * TSLOT; sa.lo[t] = pLo + t * TSLOT; }
    split_act_all<<<dim3(1, SPAD, 6), 256>>>(sa);

    // 2) fused weight transforms
    WArgs wa;
    wa.w[0] = wq_w; wa.w[1] = wk_w; wa.w[2] = wv_w; wa.w[3] = wc_w;
    wa.b[0] = wq_b; wa.b[1] = wk_b; wa.b[2] = wv_b; wa.b[3] = wc_b;
    wa.out[0] = pWq; wa.out[1] = pWk; wa.out[2] = pWv; wa.out[3] = pWc;
    wa.bP[0] = pbq; wa.bP[1] = pbk; wa.bP[2] = pbv; wa.bP[3] = pbc;
    wa.KS[0] = 3; wa.KS[1] = 3; wa.KS[2] = 1; wa.KS[3] = 1;
    wa.perm[0] = 1; wa.perm[1] = 1; wa.perm[2] = 1; wa.perm[3] = 0;
    transform_w_all<<<dim3(DMODEL, 4), 256>>>(wa);

    // 3) fused q/k/v projections: q,k -> split bf16; v -> single fp16
    GArgs gq = {};
    for (int t = 0; t < 3; t++) {
        gq.Ah[t] = pHi + t * TSLOT; gq.Al[t] = pLo + t * TSLOT;
    }
    gq.Ch[0] = pQKVh + 0 * TSLOT; gq.Cl[0] = pQKVl + 0 * TSLOT;
    gq.Ch[1] = pQKVh + 1 * TSLOT; gq.Cl[1] = pQKVl + 1 * TSLOT;
    gq.Ch[2] = pVf;               gq.Cl[2] = nullptr;
    gq.Bw[0] = pWq; gq.Bw[1] = pWk; gq.Bw[2] = pWv;
    gq.bias[0] = pbq; gq.bias[1] = pbk; gq.bias[2] = pbv;
    gq.Cf = nullptr;
    gq.KS[0] = 3; gq.KS[1] = 3; gq.KS[2] = 1;
    gq.outMode[0] = 0; gq.outMode[1] = 0; gq.outMode[2] = 1;
    gemm_hmma_kernel<<<dim3(DMODEL / 256, (BATCH * SEQ) / 128, 3), 256, GEMM_SMEM>>>(gq);

    // 4) HMMA attention (round-10 version)
    dim3 gattn(SEQ / 64, NHEAD, BATCH);
    attn_hmma_kernel<<<gattn, 256, AT_SMEM>>>(pQKVh + 0 * TSLOT, pQKVl + 0 * TSLOT,
                                              pQKVh + 1 * TSLOT, pQKVl + 1 * TSLOT,
                                              pVf, pAOh, pAOl);

    // 5) output linear -> d_out (fp32, 3-term bf16)
    GArgs gc = {};
    gc.Ah[0] = pAOh; gc.Al[0] = pAOl;
    gc.Bw[0] = pWc; gc.bias[0] = pbc;
    gc.Cf = (float*)d_out;
    gc.KS[0] = 1;
    gc.outMode[0] = 2;
    gemm_hmma_kernel<<<dim3(DMODEL / 256, (BATCH * SEQ) / 128, 1), 256, GEMM_SMEM>>>(gc);
}

// round 13
// speedup vs baseline: 1.7869x; 1.7869x over previous
#include <cuda_runtime.h>
#include <cuda_bf16.h>
#include <cuda_fp16.h>
#include <cstdint>
#include <cstddef>

#define BATCH 2
#define SEQ 2048
#define SPAD 2050
#define DMODEL 1024
#define NHEAD 16
#define PADROWS (BATCH * SPAD)

// ===========================================================================
// Scratch
// ===========================================================================
__device__ __nv_bfloat16 g_hi[3 * PADROWS * DMODEL];   // q,k split hi (+v unused slot)
__device__ __nv_bfloat16 g_lo[3 * PADROWS * DMODEL];
__device__ __half        g_vact[PADROWS * DMODEL];     // v activation fp16
__device__ __nv_bfloat16 g_qkvh[2 * PADROWS * DMODEL]; // q,k hi
__device__ __nv_bfloat16 g_qkvl[2 * PADROWS * DMODEL]; // q,k lo
__device__ __half        g_vf[PADROWS * DMODEL];       // projected v fp16
__device__ __half        g_aof[PADROWS * DMODEL];      // attention out fp16
__device__ __nv_bfloat16 g_Wqc[DMODEL * 6144];   // {Whi x3 taps, Wlo x3 taps}
__device__ __nv_bfloat16 g_Wkc[DMODEL * 6144];
__device__ __half        g_Wvf[DMODEL * 1024];   // fp16 single
__device__ __half        g_Wcf[DMODEL * 1024];   // fp16 single
__device__ float g_bq[DMODEL], g_bk[DMODEL], g_bv[DMODEL], g_bc[DMODEL];

// ===========================================================================
// PTX helpers (sm_80-era only; valid on compute_103)
// ===========================================================================
__device__ __forceinline__ uint32_t smem_to_u32(const void* p) {
    uint32_t a;
    asm("{ .reg .u64 t; cvta.to.shared.u64 t, %1; cvt.u32.u64 %0, t; }" : "=r"(a) : "l"(p));
    return a;
}
__device__ __forceinline__ void cp16(uint32_t dst, const void* src) {
    asm volatile("cp.async.cg.shared.global [%0], [%1], 16;" :: "r"(dst), "l"(src));
}
__device__ __forceinline__ void ldsm_x4(uint32_t* r, uint32_t addr) {
    asm volatile("ldmatrix.sync.aligned.m8n8.x4.shared.b16 {%0,%1,%2,%3}, [%4];"
        : "=r"(r[0]), "=r"(r[1]), "=r"(r[2]), "=r"(r[3]) : "r"(addr));
}
__device__ __forceinline__ void ldsm_x4_t(uint32_t* r, uint32_t addr) {
    asm volatile("ldmatrix.sync.aligned.m8n8.x4.trans.shared.b16 {%0,%1,%2,%3}, [%4];"
        : "=r"(r[0]), "=r"(r[1]), "=r"(r[2]), "=r"(r[3]) : "r"(addr));
}
__device__ __forceinline__ void mma_bf16(float* d, const uint32_t* a, const uint32_t* b) {
    asm volatile(
        "mma.sync.aligned.m16n8k16.row.col.f32.bf16.bf16.f32 "
        "{%0,%1,%2,%3}, {%4,%5,%6,%7}, {%8,%9}, {%0,%1,%2,%3};"
        : "+f"(d[0]), "+f"(d[1]), "+f"(d[2]), "+f"(d[3])
        : "r"(a[0]), "r"(a[1]), "r"(a[2]), "r"(a[3]), "r"(b[0]), "r"(b[1]));
}
__device__ __forceinline__ void mma_f16(float* d, const uint32_t* a, const uint32_t* b) {
    asm volatile(
        "mma.sync.aligned.m16n8k16.row.col.f32.f16.f16.f32 "
        "{%0,%1,%2,%3}, {%4,%5,%6,%7}, {%8,%9}, {%0,%1,%2,%3};"
        : "+f"(d[0]), "+f"(d[1]), "+f"(d[2]), "+f"(d[3])
        : "r"(a[0]), "r"(a[1]), "r"(a[2]), "r"(a[3]), "r"(b[0]), "r"(b[1]));
}
__device__ __forceinline__ uint32_t pack_bf16(float lo, float hi) {
    uint32_t r; asm("cvt.rn.bf16x2.f32 %0, %1, %2;" : "=r"(r) : "f"(hi), "f"(lo)); return r;
}
__device__ __forceinline__ uint32_t pack_f16(float lo, float hi) {
    uint32_t r; asm("cvt.rn.f16x2.f32 %0, %1, %2;" : "=r"(r) : "f"(hi), "f"(lo)); return r;
}
__device__ __forceinline__ float f_low(uint32_t r)  { return __uint_as_float(r << 16); }
__device__ __forceinline__ float f_high(uint32_t r) { return __uint_as_float(r & 0xffff0000u); }
__device__ __forceinline__ float ex2f(float x) {
    float r; asm("ex2.approx.f32 %0, %1;" : "=f"(r) : "f"(x)); return r;
}
__device__ __forceinline__ void split_pair(float v0, float v1, uint32_t& h2, uint32_t& l2) {
    h2 = pack_bf16(v0, v1);
    l2 = pack_bf16(v0 - f_low(h2), v1 - f_high(h2));
}

// ===========================================================================
// Fused prep: split q,k into bf16 hi/lo; v into fp16 single.
// grid (1, SPAD, 6): z = b + 2*t
// ===========================================================================
struct SArgs {
    const float* X[3];
    __nv_bfloat16* hi[2]; __nv_bfloat16* lo[2];
    __half* vf;
};

__global__ void split_act_all(SArgs sa) {
    int z = blockIdx.z;
    int t = z >> 1, b = z & 1;
    int y = blockIdx.y;
    int c = threadIdx.x << 2;
    float4 v = make_float4(0.f, 0.f, 0.f, 0.f);
    if (y >= 1 && y <= SEQ)
        v = *(const float4*)&sa.X[t][(((size_t)b * SEQ + (y - 1)) << 10) + c];
    size_t o = (((size_t)b * SPAD + y) << 10) + c;
    if (t < 2) {
        uint32_t h0, l0, h1, l1;
        split_pair(v.x, v.y, h0, l0);
        split_pair(v.z, v.w, h1, l1);
        *(uint2*)&sa.hi[t][o] = make_uint2(h0, h1);
        *(uint2*)&sa.lo[t][o] = make_uint2(l0, l1);
    } else {
        *(uint2*)&sa.vf[o] = make_uint2(pack_f16(v.x, v.y), pack_f16(v.z, v.w));
    }
}

// ===========================================================================
// Fused prep: weight transforms. grid (1024, 4).
// ws 0,1 (q,k): split bf16 {Whi x KS, Wlo x KS}. ws 2,3 (v,c): fp16 single.
// ===========================================================================
struct WArgs {
    const float* w[4]; const float* b[4];
    void* out[4]; float* bP[4];
    int KS[4]; int perm[4]; int f16[4];
};

__global__ void transform_w_all(WArgs wa) {
    int ws = blockIdx.y;
    int c = blockIdx.x;
    int i = threadIdx.x << 2;
    int KS = wa.KS[ws];
    int o = wa.perm[ws] ? ((c & 63) * 16 + (c >> 6)) : c;
    const float* src = wa.w[ws] + ((size_t)o * 1024 + i) * KS;
    if (wa.f16[ws]) {
        __half* Wf = (__half*)wa.out[ws];
        for (int tap = 0; tap < KS; tap++) {
            float v0 = src[0 * KS + tap], v1 = src[1 * KS + tap];
            float v2 = src[2 * KS + tap], v3 = src[3 * KS + tap];
            *(uint2*)&Wf[(size_t)c * (KS << 10) + ((size_t)tap << 10) + i] =
                make_uint2(pack_f16(v0, v1), pack_f16(v2, v3));
        }
    } else {
        __nv_bfloat16* Wcat = (__nv_bfloat16*)wa.out[ws];
        const int W2 = (KS << 1) << 10;
        for (int tap = 0; tap < KS; tap++) {
            float v0 = src[0 * KS + tap], v1 = src[1 * KS + tap];
            float v2 = src[2 * KS + tap], v3 = src[3 * KS + tap];
            uint32_t h0, l0, h1, l1;
            split_pair(v0, v1, h0, l0);
            split_pair(v2, v3, h1, l1);
            *(uint2*)&Wcat[(size_t)c * W2 + ((size_t)tap << 10) + i] = make_uint2(h0, h1);
            *(uint2*)&Wcat[(size_t)c * W2 + ((size_t)(KS + tap) << 10) + i] = make_uint2(l0, l1);
        }
    }
    if (threadIdx.x == 0) wa.bP[ws][c] = wa.b[ws][o];
}

// ===========================================================================
// HMMA conv-GEMM v4 (R10 base) + fp16 single-term mode.
// BM=128, BN=128, 2 CTAs/SM, 8 warps (4m x 2n), warp tile 32x64.
// f16mode: A single fp16 matrix, W fp16 single {KS taps}; NSEG = KS,
// mma_f16, no lo pass.  bf16 mode: exact R10 3-term schedule.
// ===========================================================================
#define G4_AMAT 18720
#define G4_ABUF (2 * G4_AMAT)
#define G4_AREG (2 * G4_ABUF)
#define G4_BTILE 18432
#define GEMM_SMEM (G4_AREG + 2 * G4_BTILE)

struct GArgs {
    const void* Ah[3]; const __nv_bfloat16* Al[3];
    const void* Bw[3]; const float* bias[3];
    void* Ch[3]; __nv_bfloat16* Cl[3];
    float* Cf;
    int KS[3];
    int outMode[3];   // 0: split bf16, 1: fp16, 2: fp32
    int f16mode[3];
};

__global__ void __launch_bounds__(256, 2) gemm_hmma_kernel(GArgs ga)
{
    extern __shared__ __align__(128) char smem[];
    const uint32_t sb = smem_to_u32(smem);
    const int tid = threadIdx.x, wid = tid >> 5, lane = tid & 31;
    const int z = blockIdx.z;
    const char* __restrict__ Ahi = (const char*)ga.Ah[z];       // bf16 hi or fp16
    const __nv_bfloat16* __restrict__ Alo = ga.Al[z];
    const char* __restrict__ Bw  = (const char*)ga.Bw[z];
    const float* __restrict__ bP = ga.bias[z];
    const int KS = ga.KS[z];
    const int f16 = ga.f16mode[z];

    const int row0 = blockIdx.y << 7;
    const int col0 = blockIdx.x << 7;
    const int bb = row0 >> 11;
    const size_t base = (size_t)bb * SPAD + (row0 & 2047);
    const int NSEG = f16 ? KS : (KS << 1);
    const int Kp = NSEG << 10;                  // elements per B row
    const int J = NSEG << 4;
    const int tapAdd = (KS == 1) ? 1 : 0;
    const int wm = (wid >> 1) << 5;
    const int wn = (wid & 1) << 6;

    auto load_A = [&](int ch) {
        uint32_t dst = sb + (uint32_t)(ch & 1) * G4_ABUF;
        int c0 = ch << 6;
        const int nit = f16 ? 1040 : 2080;
#pragma unroll
        for (int l = 0; l < 9; l++) {
            int idx = tid + (l << 8);
            if (idx < nit) {
                int mat = 0;
                if (idx >= 1040) { idx -= 1040; mat = 1; }
                int r = idx >> 3, jc = idx & 7;
                const char* src = mat
                    ? (const char*)(Alo + (((base + r) << 10) + c0 + (jc << 3)))
                    : (Ahi + ((((base + r) << 10) + c0 + (jc << 3)) << 1));
                cp16(dst + (uint32_t)(mat * G4_AMAT + r * 144 + (jc << 4)), src);
            }
        }
    };
    auto load_B = [&](int j, int s, int ch) {
        uint32_t dst = sb + G4_AREG + (uint32_t)(j & 1) * G4_BTILE;
        size_t k0 = ((size_t)s << 10) + (ch << 6);
#pragma unroll
        for (int l = 0; l < 4; l++) {
            int idx = tid + (l << 8);
            int r = idx >> 3, jc = idx & 7;
            cp16(dst + (uint32_t)(r * 144 + (jc << 4)),
                 Bw + (((size_t)(col0 + r) * Kp + k0 + (jc << 3)) << 1));
        }
    };

    float acc[2][8][4];
#pragma unroll
    for (int mt = 0; mt < 2; mt++)
#pragma unroll
        for (int nt = 0; nt < 8; nt++)
#pragma unroll
            for (int e = 0; e < 4; e++) acc[mt][nt][e] = 0.f;

    load_A(0);
    load_B(0, 0, 0);
    asm volatile("cp.async.commit_group;");

    int s = 0, ch = 0;
    for (int j = 0; j < J; j++) {
        if (s == 0 && ch + 1 < 16) load_A(ch + 1);
        if (j + 1 < J) {
            int s2 = s + 1, ch2 = ch;
            if (s2 == NSEG) { s2 = 0; ch2++; }
            load_B(j + 1, s2, ch2);
            asm volatile("cp.async.commit_group;");
            asm volatile("cp.async.wait_group 1;");
        } else {
            asm volatile("cp.async.commit_group;");
            asm volatile("cp.async.wait_group 0;");
        }
        __syncthreads();

        const uint32_t AsmHi = sb + (uint32_t)(ch & 1) * G4_ABUF;
        const uint32_t AsmLo = AsmHi + G4_AMAT;
        const uint32_t Bsm = sb + G4_AREG + (uint32_t)(j & 1) * G4_BTILE;

        if (f16) {
            const int tap = s + tapAdd;
#pragma unroll
            for (int kk = 0; kk < 64; kk += 16) {
                uint32_t b[4][4], a[2][4];
#pragma unroll
                for (int g = 0; g < 4; g++) {
                    int nrow = wn + g * 16 + (lane & 7) + ((lane >> 4) << 3);
                    ldsm_x4(b[g], Bsm + (uint32_t)(nrow * 144 + (kk + (((lane >> 3) & 1) << 3)) * 2));
                }
#pragma unroll
                for (int mt = 0; mt < 2; mt++)
                    ldsm_x4(a[mt], AsmHi + (uint32_t)((wm + tap + mt * 16 + (lane & 15)) * 144
                            + ((lane >> 4) << 4) + kk * 2));
#pragma unroll
                for (int mt = 0; mt < 2; mt++)
#pragma unroll
                    for (int g = 0; g < 4; g++) {
                        mma_f16(acc[mt][2 * g + 0], a[mt], &b[g][0]);
                        mma_f16(acc[mt][2 * g + 1], a[mt], &b[g][2]);
                    }
            }
        } else {
            const int tap = (s < KS ? s : s - KS) + tapAdd;
            const bool doLo = (s < KS);
#pragma unroll
            for (int kk = 0; kk < 64; kk += 16) {
                uint32_t b[4][4], a[2][4];
#pragma unroll
                for (int g = 0; g < 4; g++) {
                    int nrow = wn + g * 16 + (lane & 7) + ((lane >> 4) << 3);
                    ldsm_x4(b[g], Bsm + (uint32_t)(nrow * 144 + (kk + (((lane >> 3) & 1) << 3)) * 2));
                }
#pragma unroll
                for (int mt = 0; mt < 2; mt++)
                    ldsm_x4(a[mt], AsmHi + (uint32_t)((wm + tap + mt * 16 + (lane & 15)) * 144
                            + ((lane >> 4) << 4) + kk * 2));
#pragma unroll
                for (int mt = 0; mt < 2; mt++)
#pragma unroll
                    for (int g = 0; g < 4; g++) {
                        mma_bf16(acc[mt][2 * g + 0], a[mt], &b[g][0]);
                        mma_bf16(acc[mt][2 * g + 1], a[mt], &b[g][2]);
                    }
                if (doLo) {
#pragma unroll
                    for (int mt = 0; mt < 2; mt++)
                        ldsm_x4(a[mt], AsmLo + (uint32_t)((wm + tap + mt * 16 + (lane & 15)) * 144
                                + ((lane >> 4) << 4) + kk * 2));
#pragma unroll
                    for (int mt = 0; mt < 2; mt++)
#pragma unroll
                        for (int g = 0; g < 4; g++) {
                            mma_bf16(acc[mt][2 * g + 0], a[mt], &b[g][0]);
                            mma_bf16(acc[mt][2 * g + 1], a[mt], &b[g][2]);
                        }
                }
            }
        }
        __syncthreads();
        if (++s == NSEG) { s = 0; ch++; }
    }

    const int om = ga.outMode[z];
    if (om == 0) {
        __nv_bfloat16* __restrict__ Chi = (__nv_bfloat16*)ga.Ch[z];
        __nv_bfloat16* __restrict__ Clo = ga.Cl[z];
        const int prow0 = bb * SPAD + (row0 & 2047) + 1;
#pragma unroll
        for (int mt = 0; mt < 2; mt++) {
            int rl = wm + mt * 16 + (lane >> 2);
#pragma unroll
            for (int nt = 0; nt < 8; nt++) {
                int c = col0 + wn + nt * 8 + ((lane & 3) << 1);
                float2 bv = *(const float2*)&bP[c];
                uint32_t h2, l2;
                split_pair(acc[mt][nt][0] + bv.x, acc[mt][nt][1] + bv.y, h2, l2);
                size_t o0 = ((size_t)(prow0 + rl) << 10) + c;
                *(uint32_t*)&Chi[o0] = h2;
                *(uint32_t*)&Clo[o0] = l2;
                split_pair(acc[mt][nt][2] + bv.x, acc[mt][nt][3] + bv.y, h2, l2);
                size_t o1 = ((size_t)(prow0 + rl + 8) << 10) + c;
                *(uint32_t*)&Chi[o1] = h2;
                *(uint32_t*)&Clo[o1] = l2;
            }
        }
    } else if (om == 1) {
        __half* __restrict__ Cv = (__half*)ga.Ch[z];
        const int prow0 = bb * SPAD + (row0 & 2047) + 1;
#pragma unroll
        for (int mt = 0; mt < 2; mt++) {
            int rl = wm + mt * 16 + (lane >> 2);
#pragma unroll
            for (int nt = 0; nt < 8; nt++) {
                int c = col0 + wn + nt * 8 + ((lane & 3) << 1);
                float2 bv = *(const float2*)&bP[c];
                uint32_t p0 = pack_f16(acc[mt][nt][0] + bv.x, acc[mt][nt][1] + bv.y);
                uint32_t p1 = pack_f16(acc[mt][nt][2] + bv.x, acc[mt][nt][3] + bv.y);
                *(uint32_t*)&Cv[((size_t)(prow0 + rl) << 10) + c] = p0;
                *(uint32_t*)&Cv[((size_t)(prow0 + rl + 8) << 10) + c] = p1;
            }
        }
    } else {
        float* __restrict__ Cf = ga.Cf;
#pragma unroll
        for (int mt = 0; mt < 2; mt++) {
            int r = row0 + wm + mt * 16 + (lane >> 2);
#pragma unroll
            for (int nt = 0; nt < 8; nt++) {
                int c = col0 + wn + nt * 8 + ((lane & 3) << 1);
                float2 bv = *(const float2*)&bP[c];
                *(float2*)&Cf[(size_t)r * 1024 + c] =
                    make_float2(acc[mt][nt][0] + bv.x, acc[mt][nt][1] + bv.y);
                *(float2*)&Cf[(size_t)(r + 8) * 1024 + c] =
                    make_float2(acc[mt][nt][2] + bv.x, acc[mt][nt][3] + bv.y);
            }
        }
    }
}

// ===========================================================================
// HMMA flash attention (R10 version; output now single fp16)
// ===========================================================================
#define AT_QREG 18432
#define AT_KVBUF 27648
#define AT_SMEM (AT_QREG + 2 * AT_KVBUF + 1024)

__global__ void __launch_bounds__(256, 2) attn_hmma_kernel(
    const __nv_bfloat16* __restrict__ Qh, const __nv_bfloat16* __restrict__ Ql,
    const __nv_bfloat16* __restrict__ Kh, const __nv_bfloat16* __restrict__ Kl,
    const __half* __restrict__ Vf,
    __half* __restrict__ Of)
{
    extern __shared__ __align__(128) char smem[];
    const uint32_t sb = smem_to_u32(smem);
    const uint32_t sKV = sb + AT_QREG;
    float* rs2 = (float*)(smem + AT_QREG + 2 * AT_KVBUF);
    float* outcmb = (float*)(smem + AT_QREG);

    const int tid = threadIdx.x, wid = tid >> 5, lane = tid & 31;
    const int wm = (wid >> 1) << 4;
    const int wnk = (wid & 1) << 5;
    const int q0 = blockIdx.x << 6;
    const int h = blockIdx.y, b = blockIdx.z;
    const size_t hoff = (size_t)h * 64;
    const size_t rowbase = (size_t)b * SPAD + 1;

#pragma unroll
    for (int l = 0; l < 4; l++) {
        int mat = l >> 1;
        int r = (tid >> 3) + ((l & 1) << 5);
        int j = tid & 7;
        const __nv_bfloat16* src = (mat ? Ql : Qh) + (((rowbase + q0 + r) << 10) + hoff + (j << 3));
        cp16(sb + (uint32_t)(mat * 9216 + r * 144 + j * 16), src);
    }
    asm volatile("cp.async.commit_group;");

    auto loadKV = [&](int c) {
        uint32_t dstb = sKV + (uint32_t)(c & 1) * AT_KVBUF;
        size_t krow = rowbase + ((size_t)c << 6);
#pragma unroll
        for (int l = 0; l < 6; l++) {
            int mat = l >> 1;
            int r = (tid >> 3) + ((l & 1) << 5);
            int j = tid & 7;
            const void* src;
            if (mat == 0)      src = Kh + (((krow + r) << 10) + hoff + (j << 3));
            else if (mat == 1) src = Kl + (((krow + r) << 10) + hoff + (j << 3));
            else               src = Vf + (((krow + r) << 10) + hoff + (j << 3));
            cp16(dstb + (uint32_t)(mat * 9216 + r * 144 + j * 16), src);
        }
    };
    loadKV(0);
    asm volatile("cp.async.commit_group;");

    float outacc[8][4];
    float rs[2] = {0.f, 0.f};
#pragma unroll
    for (int nt = 0; nt < 8; nt++)
#pragma unroll
        for (int e = 0; e < 4; e++) outacc[nt][e] = 0.f;

    const float CEXP = 1.4426950408889634f * 0.125f;
    const float EBIAS = 17.312340490667562f;

    for (int c = 0; c < 32; c++) {
        if (c + 1 < 32) {
            loadKV(c + 1);
            asm volatile("cp.async.commit_group;");
            asm volatile("cp.async.wait_group 1;");
        } else {
            asm volatile("cp.async.wait_group 0;");
        }
        __syncthreads();
        uint32_t bufb = sKV + (uint32_t)(c & 1) * AT_KVBUF;

        float sc[4][4];
#pragma unroll
        for (int nt = 0; nt < 4; nt++)
#pragma unroll
            for (int e = 0; e < 4; e++) sc[nt][e] = 0.f;

#pragma unroll
        for (int ks = 0; ks < 4; ks++) {
            uint32_t ah[4], al[4], bh[2][4], bl[2][4];
            uint32_t qaddr = sb + (uint32_t)((wm + (lane & 15)) * 144
                             + ((lane >> 4) << 4) + ks * 32);
            ldsm_x4(ah, qaddr);
            ldsm_x4(al, qaddr + 9216);
#pragma unroll
            for (int g = 0; g < 2; g++) {
                int nrow = wnk + g * 16 + (lane & 7) + ((lane >> 4) << 3);
                uint32_t kaddr = bufb + (uint32_t)(nrow * 144 + ks * 32 + (((lane >> 3) & 1) << 4));
                ldsm_x4(bh[g], kaddr);
                ldsm_x4(bl[g], kaddr + 9216);
            }
#pragma unroll
            for (int g = 0; g < 2; g++) {
                mma_bf16(sc[2 * g + 0], ah, &bh[g][0]);
                mma_bf16(sc[2 * g + 1], ah, &bh[g][2]);
                mma_bf16(sc[2 * g + 0], ah, &bl[g][0]);
                mma_bf16(sc[2 * g + 1], ah, &bl[g][2]);
                mma_bf16(sc[2 * g + 0], al, &bh[g][0]);
                mma_bf16(sc[2 * g + 1], al, &bh[g][2]);
            }
        }

        uint32_t phi[2][4];
#pragma unroll
        for (int nt = 0; nt < 4; nt++)
#pragma unroll
            for (int e = 0; e < 4; e++) {
                float p = ex2f(sc[nt][e] * CEXP - EBIAS);
                sc[nt][e] = p;
                rs[e >> 1] += p;
            }
#pragma unroll
        for (int kt = 0; kt < 2; kt++) {
            phi[kt][0] = pack_f16(sc[2 * kt][0], sc[2 * kt][1]);
            phi[kt][1] = pack_f16(sc[2 * kt][2], sc[2 * kt][3]);
            phi[kt][2] = pack_f16(sc[2 * kt + 1][0], sc[2 * kt + 1][1]);
            phi[kt][3] = pack_f16(sc[2 * kt + 1][2], sc[2 * kt + 1][3]);
        }

#pragma unroll
        for (int kt = 0; kt < 2; kt++) {
            uint32_t vh[4][4];
#pragma unroll
            for (int g = 0; g < 4; g++) {
                int keyrow = wnk + kt * 16 + (lane & 7) + (((lane >> 3) & 1) << 3);
                uint32_t vaddr = bufb + 18432
                               + (uint32_t)(keyrow * 144 + g * 32 + ((lane >> 4) << 4));
                ldsm_x4_t(vh[g], vaddr);
            }
#pragma unroll
            for (int g = 0; g < 4; g++) {
                mma_f16(outacc[2 * g + 0], phi[kt], &vh[g][0]);
                mma_f16(outacc[2 * g + 1], phi[kt], &vh[g][2]);
            }
        }
        __syncthreads();
    }

#pragma unroll
    for (int hf = 0; hf < 2; hf++) {
        rs[hf] += __shfl_xor_sync(0xffffffffu, rs[hf], 1);
        rs[hf] += __shfl_xor_sync(0xffffffffu, rs[hf], 2);
    }
    if ((lane & 3) == 0) {
#pragma unroll
        for (int hf = 0; hf < 2; hf++)
            rs2[(wm + (lane >> 2) + hf * 8) * 2 + (wid & 1)] = rs[hf];
    }
    if (wid & 1) {
#pragma unroll
        for (int nt = 0; nt < 8; nt++)
#pragma unroll
            for (int e = 0; e < 4; e++) {
                int row = wm + (lane >> 2) + (e >> 1) * 8;
                int col = nt * 8 + ((lane & 3) << 1) + (e & 1);
                outcmb[row * 66 + col] = outacc[nt][e];
            }
    }
    __syncthreads();
    if (!(wid & 1)) {
        int r0 = wm + (lane >> 2);
#pragma unroll
        for (int hf = 0; hf < 2; hf++) {
            int row = r0 + hf * 8;
            float inv = 1.f / (rs2[row * 2] + rs2[row * 2 + 1]);
            size_t grow = ((rowbase + q0 + row) << 10) + hoff;
#pragma unroll
            for (int nt = 0; nt < 8; nt++) {
                int col = nt * 8 + ((lane & 3) << 1);
                float v0 = (outacc[nt][hf * 2 + 0] + outcmb[row * 66 + col]) * inv;
                float v1 = (outacc[nt][hf * 2 + 1] + outcmb[row * 66 + col + 1]) * inv;
                *(uint32_t*)&Of[grow + col] = pack_f16(v0, v1);
            }
        }
    }
}

// ===========================================================================
// Launch
// ===========================================================================
extern "C" void kernel_launch(void* const* d_in, const int* in_sizes, int n_in,
                              void* d_out, int out_size) {
    const float* q    = (const float*)d_in[0];
    const float* k    = (const float*)d_in[1];
    const float* v    = (const float*)d_in[2];
    const float* wq_w = (const float*)d_in[3];
    const float* wq_b = (const float*)d_in[4];
    const float* wk_w = (const float*)d_in[5];
    const float* wk_b = (const float*)d_in[6];
    const float* wv_w = (const float*)d_in[7];
    const float* wv_b = (const float*)d_in[8];
    const float* wc_w = (const float*)d_in[9];
    const float* wc_b = (const float*)d_in[10];

    __nv_bfloat16 *pHi, *pLo, *pQKVh, *pQKVl, *pWq, *pWk;
    __half *pVact, *pVf, *pAOf, *pWvf, *pWcf;
    float *pbq, *pbk, *pbv, *pbc;
    cudaGetSymbolAddress((void**)&pHi, g_hi);
    cudaGetSymbolAddress((void**)&pLo, g_lo);
    cudaGetSymbolAddress((void**)&pVact, g_vact);
    cudaGetSymbolAddress((void**)&pQKVh, g_qkvh);
    cudaGetSymbolAddress((void**)&pQKVl, g_qkvl);
    cudaGetSymbolAddress((void**)&pVf, g_vf);
    cudaGetSymbolAddress((void**)&pAOf, g_aof);
    cudaGetSymbolAddress((void**)&pWq, g_Wqc);
    cudaGetSymbolAddress((void**)&pWk, g_Wkc);
    cudaGetSymbolAddress((void**)&pWvf, g_Wvf);
    cudaGetSymbolAddress((void**)&pWcf, g_Wcf);
    cudaGetSymbolAddress((void**)&pbq, g_bq);
    cudaGetSymbolAddress((void**)&pbk, g_bk);
    cudaGetSymbolAddress((void**)&pbv, g_bv);
    cudaGetSymbolAddress((void**)&pbc, g_bc);

    const int TSLOT = PADROWS * DMODEL;

    cudaFuncSetAttribute(gemm_hmma_kernel, cudaFuncAttributeMaxDynamicSharedMemorySize, GEMM_SMEM);
    cudaFuncSetAttribute(attn_hmma_kernel, cudaFuncAttributeMaxDynamicSharedMemorySize, AT_SMEM);

    // 1) fused activation split (q,k -> bf16 hi/lo; v -> fp16)
    SArgs sa;
    sa.X[0] = q; sa.X[1] = k; sa.X[2] = v;
    for (int t = 0; t < 2; t++) { sa.hi[t] = pHi + t * TSLOT; sa.lo[t] = pLo + t * TSLOT; }
    sa.vf = pVact;
    split_act_all<<<dim3(1, SPAD, 6), 256>>>(sa);

    // 2) fused weight transforms (q,k split bf16; v,c fp16 single)
    WArgs wa;
    wa.w[0] = wq_w; wa.w[1] = wk_w; wa.w[2] = wv_w; wa.w[3] = wc_w;
    wa.b[0] = wq_b; wa.b[1] = wk_b; wa.b[2] = wv_b; wa.b[3] = wc_b;
    wa.out[0] = pWq; wa.out[1] = pWk; wa.out[2] = pWvf; wa.out[3] = pWcf;
    wa.bP[0] = pbq; wa.bP[1] = pbk; wa.bP[2] = pbv; wa.bP[3] = pbc;
    wa.KS[0] = 3; wa.KS[1] = 3; wa.KS[2] = 1; wa.KS[3] = 1;
    wa.perm[0] = 1; wa.perm[1] = 1; wa.perm[2] = 1; wa.perm[3] = 0;
    wa.f16[0] = 0; wa.f16[1] = 0; wa.f16[2] = 1; wa.f16[3] = 1;
    transform_w_all<<<dim3(DMODEL, 4), 256>>>(wa);

    // 3) fused q/k/v projections: q,k 3-term bf16 -> split out; v fp16 single -> fp16 out
    GArgs gq = {};
    gq.Ah[0] = pHi + 0 * TSLOT; gq.Al[0] = pLo + 0 * TSLOT;
    gq.Ah[1] = pHi + 1 * TSLOT; gq.Al[1] = pLo + 1 * TSLOT;
    gq.Ah[2] = pVact;           gq.Al[2] = nullptr;
    gq.Ch[0] = pQKVh + 0 * TSLOT; gq.Cl[0] = pQKVl + 0 * TSLOT;
    gq.Ch[1] = pQKVh + 1 * TSLOT; gq.Cl[1] = pQKVl + 1 * TSLOT;
    gq.Ch[2] = pVf;               gq.Cl[2] = nullptr;
    gq.Bw[0] = pWq; gq.Bw[1] = pWk; gq.Bw[2] = pWvf;
    gq.bias[0] = pbq; gq.bias[1] = pbk; gq.bias[2] = pbv;
    gq.Cf = nullptr;
    gq.KS[0] = 3; gq.KS[1] = 3; gq.KS[2] = 1;
    gq.outMode[0] = 0; gq.outMode[1] = 0; gq.outMode[2] = 1;
    gq.f16mode[0] = 0; gq.f16mode[1] = 0; gq.f16mode[2] = 1;
    gemm_hmma_kernel<<<dim3(DMODEL / 128, (BATCH * SEQ) / 128, 3), 256, GEMM_SMEM>>>(gq);

    // 4) HMMA attention (fp16 output)
    dim3 gattn(SEQ / 64, NHEAD, BATCH);
    attn_hmma_kernel<<<gattn, 256, AT_SMEM>>>(pQKVh + 0 * TSLOT, pQKVl + 0 * TSLOT,
                                              pQKVh + 1 * TSLOT, pQKVl + 1 * TSLOT,
                                              pVf, pAOf);

    // 5) output linear -> d_out (fp32 out, fp16 single-term)
    GArgs gc = {};
    gc.Ah[0] = pAOf; gc.Al[0] = nullptr;
    gc.Bw[0] = pWcf; gc.bias[0] = pbc;
    gc.Cf = (float*)d_out;
    gc.KS[0] = 1;
    gc.outMode[0] = 2;
    gc.f16mode[0] = 1;
    gemm_hmma_kernel<<<dim3(DMODEL / 128, (BATCH * SEQ) / 128, 1), 256, GEMM_SMEM>>>(gc);
}

// round 15
// speedup vs baseline: 1.9238x; 1.0766x over previous
#include <cuda_runtime.h>
#include <cuda_bf16.h>
#include <cuda_fp16.h>
#include <cstdint>
#include <cstddef>

#define BATCH 2
#define SEQ 2048
#define SPAD 2050
#define DMODEL 1024
#define NHEAD 16
#define PADROWS (BATCH * SPAD)

// ===========================================================================
// Scratch
// ===========================================================================
__device__ __nv_bfloat16 g_hi[2 * PADROWS * DMODEL];   // q,k act split hi
__device__ __nv_bfloat16 g_lo[2 * PADROWS * DMODEL];
__device__ __half        g_vact[PADROWS * DMODEL];     // v activation fp16
__device__ __half        g_qfh[PADROWS * DMODEL];      // projected q fp16 hi
__device__ __half        g_qfl[PADROWS * DMODEL];      // projected q fp16 lo
__device__ __half        g_kf[PADROWS * DMODEL];       // projected k fp16 single
__device__ __half        g_vf[PADROWS * DMODEL];       // projected v fp16
__device__ __half        g_aof[PADROWS * DMODEL];      // attention out fp16
__device__ __nv_bfloat16 g_Wqc[DMODEL * 6144];   // {Whi x3 taps, Wlo x3 taps}
__device__ __nv_bfloat16 g_Wkc[DMODEL * 6144];
__device__ __half        g_Wvf[DMODEL * 1024];   // fp16 single
__device__ __half        g_Wcf[DMODEL * 1024];
__device__ float g_bq[DMODEL], g_bk[DMODEL], g_bv[DMODEL], g_bc[DMODEL];

// ===========================================================================
// PTX helpers
// ===========================================================================
__device__ __forceinline__ uint32_t smem_to_u32(const void* p) {
    uint32_t a;
    asm("{ .reg .u64 t; cvta.to.shared.u64 t, %1; cvt.u32.u64 %0, t; }" : "=r"(a) : "l"(p));
    return a;
}
__device__ __forceinline__ void cp16(uint32_t dst, const void* src) {
    asm volatile("cp.async.cg.shared.global [%0], [%1], 16;" :: "r"(dst), "l"(src));
}
__device__ __forceinline__ void ldsm_x4(uint32_t* r, uint32_t addr) {
    asm volatile("ldmatrix.sync.aligned.m8n8.x4.shared.b16 {%0,%1,%2,%3}, [%4];"
        : "=r"(r[0]), "=r"(r[1]), "=r"(r[2]), "=r"(r[3]) : "r"(addr));
}
__device__ __forceinline__ void ldsm_x4_t(uint32_t* r, uint32_t addr) {
    asm volatile("ldmatrix.sync.aligned.m8n8.x4.trans.shared.b16 {%0,%1,%2,%3}, [%4];"
        : "=r"(r[0]), "=r"(r[1]), "=r"(r[2]), "=r"(r[3]) : "r"(addr));
}
__device__ __forceinline__ void mma_bf16(float* d, const uint32_t* a, const uint32_t* b) {
    asm volatile(
        "mma.sync.aligned.m16n8k16.row.col.f32.bf16.bf16.f32 "
        "{%0,%1,%2,%3}, {%4,%5,%6,%7}, {%8,%9}, {%0,%1,%2,%3};"
        : "+f"(d[0]), "+f"(d[1]), "+f"(d[2]), "+f"(d[3])
        : "r"(a[0]), "r"(a[1]), "r"(a[2]), "r"(a[3]), "r"(b[0]), "r"(b[1]));
}
__device__ __forceinline__ void mma_f16(float* d, const uint32_t* a, const uint32_t* b) {
    asm volatile(
        "mma.sync.aligned.m16n8k16.row.col.f32.f16.f16.f32 "
        "{%0,%1,%2,%3}, {%4,%5,%6,%7}, {%8,%9}, {%0,%1,%2,%3};"
        : "+f"(d[0]), "+f"(d[1]), "+f"(d[2]), "+f"(d[3])
        : "r"(a[0]), "r"(a[1]), "r"(a[2]), "r"(a[3]), "r"(b[0]), "r"(b[1]));
}
__device__ __forceinline__ uint32_t pack_bf16(float lo, float hi) {
    uint32_t r; asm("cvt.rn.bf16x2.f32 %0, %1, %2;" : "=r"(r) : "f"(hi), "f"(lo)); return r;
}
__device__ __forceinline__ uint32_t pack_f16(float lo, float hi) {
    uint32_t r; asm("cvt.rn.f16x2.f32 %0, %1, %2;" : "=r"(r) : "f"(hi), "f"(lo)); return r;
}
__device__ __forceinline__ float f_low(uint32_t r)  { return __uint_as_float(r << 16); }
__device__ __forceinline__ float f_high(uint32_t r) { return __uint_as_float(r & 0xffff0000u); }
__device__ __forceinline__ float ex2f(float x) {
    float r; asm("ex2.approx.f32 %0, %1;" : "=f"(r) : "f"(x)); return r;
}
__device__ __forceinline__ void split_pair(float v0, float v1, uint32_t& h2, uint32_t& l2) {
    h2 = pack_bf16(v0, v1);
    l2 = pack_bf16(v0 - f_low(h2), v1 - f_high(h2));
}
__device__ __forceinline__ void split_pair_f16(float v0, float v1, uint32_t& h2, uint32_t& l2) {
    h2 = pack_f16(v0, v1);
    __half2 p = *(__half2*)&h2;
    l2 = pack_f16(v0 - __low2float(p), v1 - __high2float(p));
}

// ===========================================================================
// Fused prep: q,k -> bf16 hi/lo; v -> fp16. grid (1, SPAD, 6)
// ===========================================================================
struct SArgs {
    const float* X[3];
    __nv_bfloat16* hi[2]; __nv_bfloat16* lo[2];
    __half* vf;
};

__global__ void split_act_all(SArgs sa) {
    int z = blockIdx.z;
    int t = z >> 1, b = z & 1;
    int y = blockIdx.y;
    int c = threadIdx.x << 2;
    float4 v = make_float4(0.f, 0.f, 0.f, 0.f);
    if (y >= 1 && y <= SEQ)
        v = *(const float4*)&sa.X[t][(((size_t)b * SEQ + (y - 1)) << 10) + c];
    size_t o = (((size_t)b * SPAD + y) << 10) + c;
    if (t < 2) {
        uint32_t h0, l0, h1, l1;
        split_pair(v.x, v.y, h0, l0);
        split_pair(v.z, v.w, h1, l1);
        *(uint2*)&sa.hi[t][o] = make_uint2(h0, h1);
        *(uint2*)&sa.lo[t][o] = make_uint2(l0, l1);
    } else {
        *(uint2*)&sa.vf[o] = make_uint2(pack_f16(v.x, v.y), pack_f16(v.z, v.w));
    }
}

// ===========================================================================
// Fused prep: weight transforms. grid (1024, 4).
// ws 0,1 (q,k): split bf16. ws 2,3 (v,c): fp16 single.
// ===========================================================================
struct WArgs {
    const float* w[4]; const float* b[4];
    void* out[4]; float* bP[4];
    int KS[4]; int perm[4]; int f16[4];
};

__global__ void transform_w_all(WArgs wa) {
    int ws = blockIdx.y;
    int c = blockIdx.x;
    int i = threadIdx.x << 2;
    int KS = wa.KS[ws];
    int o = wa.perm[ws] ? ((c & 63) * 16 + (c >> 6)) : c;
    const float* src = wa.w[ws] + ((size_t)o * 1024 + i) * KS;
    if (wa.f16[ws]) {
        __half* Wf = (__half*)wa.out[ws];
        for (int tap = 0; tap < KS; tap++) {
            float v0 = src[0 * KS + tap], v1 = src[1 * KS + tap];
            float v2 = src[2 * KS + tap], v3 = src[3 * KS + tap];
            *(uint2*)&Wf[(size_t)c * (KS << 10) + ((size_t)tap << 10) + i] =
                make_uint2(pack_f16(v0, v1), pack_f16(v2, v3));
        }
    } else {
        __nv_bfloat16* Wcat = (__nv_bfloat16*)wa.out[ws];
        const int W2 = (KS << 1) << 10;
        for (int tap = 0; tap < KS; tap++) {
            float v0 = src[0 * KS + tap], v1 = src[1 * KS + tap];
            float v2 = src[2 * KS + tap], v3 = src[3 * KS + tap];
            uint32_t h0, l0, h1, l1;
            split_pair(v0, v1, h0, l0);
            split_pair(v2, v3, h1, l1);
            *(uint2*)&Wcat[(size_t)c * W2 + ((size_t)tap << 10) + i] = make_uint2(h0, h1);
            *(uint2*)&Wcat[(size_t)c * W2 + ((size_t)(KS + tap) << 10) + i] = make_uint2(l0, l1);
        }
    }
    if (threadIdx.x == 0) wa.bP[ws][c] = wa.b[ws][o];
}

// ===========================================================================
// HMMA conv-GEMM (R13 base). BM=128, BN=128, 2 CTAs/SM.
// bf16 mode: 3-term split schedule. f16mode: single fp16 pass.
// outMode 0: split fp16 (Ch,Cl as __half*), 1: single fp16, 2: fp32 dense.
// ===========================================================================
#define G4_AMAT 18720
#define G4_ABUF (2 * G4_AMAT)
#define G4_AREG (2 * G4_ABUF)
#define G4_BTILE 18432
#define GEMM_SMEM (G4_AREG + 2 * G4_BTILE)

struct GArgs {
    const void* Ah[3]; const __nv_bfloat16* Al[3];
    const void* Bw[3]; const float* bias[3];
    void* Ch[3]; void* Cl[3];
    float* Cf;
    int KS[3];
    int outMode[3];
    int f16mode[3];
};

__global__ void __launch_bounds__(256, 2) gemm_hmma_kernel(GArgs ga)
{
    extern __shared__ __align__(128) char smem[];
    const uint32_t sb = smem_to_u32(smem);
    const int tid = threadIdx.x, wid = tid >> 5, lane = tid & 31;
    const int z = blockIdx.z;
    const char* __restrict__ Ahi = (const char*)ga.Ah[z];
    const __nv_bfloat16* __restrict__ Alo = ga.Al[z];
    const char* __restrict__ Bw  = (const char*)ga.Bw[z];
    const float* __restrict__ bP = ga.bias[z];
    const int KS = ga.KS[z];
    const int f16 = ga.f16mode[z];

    const int row0 = blockIdx.y << 7;
    const int col0 = blockIdx.x << 7;
    const int bb = row0 >> 11;
    const size_t base = (size_t)bb * SPAD + (row0 & 2047);
    const int NSEG = f16 ? KS : (KS << 1);
    const int Kp = NSEG << 10;
    const int J = NSEG << 4;
    const int tapAdd = (KS == 1) ? 1 : 0;
    const int wm = (wid >> 1) << 5;
    const int wn = (wid & 1) << 6;

    auto load_A = [&](int ch) {
        uint32_t dst = sb + (uint32_t)(ch & 1) * G4_ABUF;
        int c0 = ch << 6;
        const int nit = f16 ? 1040 : 2080;
#pragma unroll
        for (int l = 0; l < 9; l++) {
            int idx = tid + (l << 8);
            if (idx < nit) {
                int mat = 0;
                if (idx >= 1040) { idx -= 1040; mat = 1; }
                int r = idx >> 3, jc = idx & 7;
                const char* src = mat
                    ? (const char*)(Alo + (((base + r) << 10) + c0 + (jc << 3)))
                    : (Ahi + ((((base + r) << 10) + c0 + (jc << 3)) << 1));
                cp16(dst + (uint32_t)(mat * G4_AMAT + r * 144 + (jc << 4)), src);
            }
        }
    };
    auto load_B = [&](int j, int s, int ch) {
        uint32_t dst = sb + G4_AREG + (uint32_t)(j & 1) * G4_BTILE;
        size_t k0 = ((size_t)s << 10) + (ch << 6);
#pragma unroll
        for (int l = 0; l < 4; l++) {
            int idx = tid + (l << 8);
            int r = idx >> 3, jc = idx & 7;
            cp16(dst + (uint32_t)(r * 144 + (jc << 4)),
                 Bw + (((size_t)(col0 + r) * Kp + k0 + (jc << 3)) << 1));
        }
    };

    float acc[2][8][4];
#pragma unroll
    for (int mt = 0; mt < 2; mt++)
#pragma unroll
        for (int nt = 0; nt < 8; nt++)
#pragma unroll
            for (int e = 0; e < 4; e++) acc[mt][nt][e] = 0.f;

    load_A(0);
    load_B(0, 0, 0);
    asm volatile("cp.async.commit_group;");

    int s = 0, ch = 0;
    for (int j = 0; j < J; j++) {
        if (s == 0 && ch + 1 < 16) load_A(ch + 1);
        if (j + 1 < J) {
            int s2 = s + 1, ch2 = ch;
            if (s2 == NSEG) { s2 = 0; ch2++; }
            load_B(j + 1, s2, ch2);
            asm volatile("cp.async.commit_group;");
            asm volatile("cp.async.wait_group 1;");
        } else {
            asm volatile("cp.async.commit_group;");
            asm volatile("cp.async.wait_group 0;");
        }
        __syncthreads();

        const uint32_t AsmHi = sb + (uint32_t)(ch & 1) * G4_ABUF;
        const uint32_t AsmLo = AsmHi + G4_AMAT;
        const uint32_t Bsm = sb + G4_AREG + (uint32_t)(j & 1) * G4_BTILE;

        if (f16) {
            const int tap = s + tapAdd;
#pragma unroll
            for (int kk = 0; kk < 64; kk += 16) {
                uint32_t b[4][4], a[2][4];
#pragma unroll
                for (int g = 0; g < 4; g++) {
                    int nrow = wn + g * 16 + (lane & 7) + ((lane >> 4) << 3);
                    ldsm_x4(b[g], Bsm + (uint32_t)(nrow * 144 + (kk + (((lane >> 3) & 1) << 3)) * 2));
                }
#pragma unroll
                for (int mt = 0; mt < 2; mt++)
                    ldsm_x4(a[mt], AsmHi + (uint32_t)((wm + tap + mt * 16 + (lane & 15)) * 144
                            + ((lane >> 4) << 4) + kk * 2));
#pragma unroll
                for (int mt = 0; mt < 2; mt++)
#pragma unroll
                    for (int g = 0; g < 4; g++) {
                        mma_f16(acc[mt][2 * g + 0], a[mt], &b[g][0]);
                        mma_f16(acc[mt][2 * g + 1], a[mt], &b[g][2]);
                    }
            }
        } else {
            const int tap = (s < KS ? s : s - KS) + tapAdd;
            const bool doLo = (s < KS);
#pragma unroll
            for (int kk = 0; kk < 64; kk += 16) {
                uint32_t b[4][4], a[2][4];
#pragma unroll
                for (int g = 0; g < 4; g++) {
                    int nrow = wn + g * 16 + (lane & 7) + ((lane >> 4) << 3);
                    ldsm_x4(b[g], Bsm + (uint32_t)(nrow * 144 + (kk + (((lane >> 3) & 1) << 3)) * 2));
                }
#pragma unroll
                for (int mt = 0; mt < 2; mt++)
                    ldsm_x4(a[mt], AsmHi + (uint32_t)((wm + tap + mt * 16 + (lane & 15)) * 144
                            + ((lane >> 4) << 4) + kk * 2));
#pragma unroll
                for (int mt = 0; mt < 2; mt++)
#pragma unroll
                    for (int g = 0; g < 4; g++) {
                        mma_bf16(acc[mt][2 * g + 0], a[mt], &b[g][0]);
                        mma_bf16(acc[mt][2 * g + 1], a[mt], &b[g][2]);
                    }
                if (doLo) {
#pragma unroll
                    for (int mt = 0; mt < 2; mt++)
                        ldsm_x4(a[mt], AsmLo + (uint32_t)((wm + tap + mt * 16 + (lane & 15)) * 144
                                + ((lane >> 4) << 4) + kk * 2));
#pragma unroll
                    for (int mt = 0; mt < 2; mt++)
#pragma unroll
                        for (int g = 0; g < 4; g++) {
                            mma_bf16(acc[mt][2 * g + 0], a[mt], &b[g][0]);
                            mma_bf16(acc[mt][2 * g + 1], a[mt], &b[g][2]);
                        }
                }
            }
        }
        __syncthreads();
        if (++s == NSEG) { s = 0; ch++; }
    }

    const int om = ga.outMode[z];
    if (om == 0) {
        __half* __restrict__ Chi = (__half*)ga.Ch[z];
        __half* __restrict__ Clo = (__half*)ga.Cl[z];
        const int prow0 = bb * SPAD + (row0 & 2047) + 1;
#pragma unroll
        for (int mt = 0; mt < 2; mt++) {
            int rl = wm + mt * 16 + (lane >> 2);
#pragma unroll
            for (int nt = 0; nt < 8; nt++) {
                int c = col0 + wn + nt * 8 + ((lane & 3) << 1);
                float2 bv = *(const float2*)&bP[c];
                uint32_t h2, l2;
                split_pair_f16(acc[mt][nt][0] + bv.x, acc[mt][nt][1] + bv.y, h2, l2);
                size_t o0 = ((size_t)(prow0 + rl) << 10) + c;
                *(uint32_t*)&Chi[o0] = h2;
                *(uint32_t*)&Clo[o0] = l2;
                split_pair_f16(acc[mt][nt][2] + bv.x, acc[mt][nt][3] + bv.y, h2, l2);
                size_t o1 = ((size_t)(prow0 + rl + 8) << 10) + c;
                *(uint32_t*)&Chi[o1] = h2;
                *(uint32_t*)&Clo[o1] = l2;
            }
        }
    } else if (om == 1) {
        __half* __restrict__ Cv = (__half*)ga.Ch[z];
        const int prow0 = bb * SPAD + (row0 & 2047) + 1;
#pragma unroll
        for (int mt = 0; mt < 2; mt++) {
            int rl = wm + mt * 16 + (lane >> 2);
#pragma unroll
            for (int nt = 0; nt < 8; nt++) {
                int c = col0 + wn + nt * 8 + ((lane & 3) << 1);
                float2 bv = *(const float2*)&bP[c];
                uint32_t p0 = pack_f16(acc[mt][nt][0] + bv.x, acc[mt][nt][1] + bv.y);
                uint32_t p1 = pack_f16(acc[mt][nt][2] + bv.x, acc[mt][nt][3] + bv.y);
                *(uint32_t*)&Cv[((size_t)(prow0 + rl) << 10) + c] = p0;
                *(uint32_t*)&Cv[((size_t)(prow0 + rl + 8) << 10) + c] = p1;
            }
        }
    } else {
        float* __restrict__ Cf = ga.Cf;
#pragma unroll
        for (int mt = 0; mt < 2; mt++) {
            int r = row0 + wm + mt * 16 + (lane >> 2);
#pragma unroll
            for (int nt = 0; nt < 8; nt++) {
                int c = col0 + wn + nt * 8 + ((lane & 3) << 1);
                float2 bv = *(const float2*)&bP[c];
                *(float2*)&Cf[(size_t)r * 1024 + c] =
                    make_float2(acc[mt][nt][0] + bv.x, acc[mt][nt][1] + bv.y);
                *(float2*)&Cf[(size_t)(r + 8) * 1024 + c] =
                    make_float2(acc[mt][nt][2] + bv.x, acc[mt][nt][3] + bv.y);
            }
        }
    }
}

// ===========================================================================
// HMMA flash attention: QK 2-term fp16 (Qhi,Qlo x K-fp16), PV single fp16.
// 64 q-rows/block, 64-key chunks, 2 CTAs/SM.
// smem: Qh/Ql 2x9216 + 2 KV bufs x (K 9216 + V 9216) + 1024 = 56320.
// ===========================================================================
#define AT_QREG 18432
#define AT_KVBUF 18432
#define AT_SMEM (AT_QREG + 2 * AT_KVBUF + 1024)   // 56320

__global__ void __launch_bounds__(256, 2) attn_hmma_kernel(
    const __half* __restrict__ Qh, const __half* __restrict__ Ql,
    const __half* __restrict__ Kf, const __half* __restrict__ Vf,
    __half* __restrict__ Of)
{
    extern __shared__ __align__(128) char smem[];
    const uint32_t sb = smem_to_u32(smem);
    const uint32_t sKV = sb + AT_QREG;
    float* rs2 = (float*)(smem + AT_QREG + 2 * AT_KVBUF);
    float* outcmb = (float*)(smem + AT_QREG);

    const int tid = threadIdx.x, wid = tid >> 5, lane = tid & 31;
    const int wm = (wid >> 1) << 4;
    const int wnk = (wid & 1) << 5;
    const int q0 = blockIdx.x << 6;
    const int h = blockIdx.y, b = blockIdx.z;
    const size_t hoff = (size_t)h * 64;
    const size_t rowbase = (size_t)b * SPAD + 1;

#pragma unroll
    for (int l = 0; l < 4; l++) {
        int mat = l >> 1;
        int r = (tid >> 3) + ((l & 1) << 5);
        int j = tid & 7;
        const __half* src = (mat ? Ql : Qh) + (((rowbase + q0 + r) << 10) + hoff + (j << 3));
        cp16(sb + (uint32_t)(mat * 9216 + r * 144 + j * 16), src);
    }
    asm volatile("cp.async.commit_group;");

    auto loadKV = [&](int c) {
        uint32_t dstb = sKV + (uint32_t)(c & 1) * AT_KVBUF;
        size_t krow = rowbase + ((size_t)c << 6);
#pragma unroll
        for (int l = 0; l < 4; l++) {
            int mat = l >> 1;                   // 0:K 1:V
            int r = (tid >> 3) + ((l & 1) << 5);
            int j = tid & 7;
            const __half* src = (mat ? Vf : Kf) + (((krow + r) << 10) + hoff + (j << 3));
            cp16(dstb + (uint32_t)(mat * 9216 + r * 144 + j * 16), src);
        }
    };
    loadKV(0);
    asm volatile("cp.async.commit_group;");

    float outacc[8][4];
    float rs[2] = {0.f, 0.f};
#pragma unroll
    for (int nt = 0; nt < 8; nt++)
#pragma unroll
        for (int e = 0; e < 4; e++) outacc[nt][e] = 0.f;

    const float CEXP = 1.4426950408889634f * 0.125f;
    const float EBIAS = 17.312340490667562f;

    for (int c = 0; c < 32; c++) {
        if (c + 1 < 32) {
            loadKV(c + 1);
            asm volatile("cp.async.commit_group;");
            asm volatile("cp.async.wait_group 1;");
        } else {
            asm volatile("cp.async.wait_group 0;");
        }
        __syncthreads();
        uint32_t bufb = sKV + (uint32_t)(c & 1) * AT_KVBUF;

        // ---- scores: 2-term fp16 (qh + ql) x k ----
        float sc[4][4];
#pragma unroll
        for (int nt = 0; nt < 4; nt++)
#pragma unroll
            for (int e = 0; e < 4; e++) sc[nt][e] = 0.f;

#pragma unroll
        for (int ks = 0; ks < 4; ks++) {
            uint32_t ah[4], al[4], bk[2][4];
            uint32_t qaddr = sb + (uint32_t)((wm + (lane & 15)) * 144
                             + ((lane >> 4) << 4) + ks * 32);
            ldsm_x4(ah, qaddr);
            ldsm_x4(al, qaddr + 9216);
#pragma unroll
            for (int g = 0; g < 2; g++) {
                int nrow = wnk + g * 16 + (lane & 7) + ((lane >> 4) << 3);
                ldsm_x4(bk[g], bufb + (uint32_t)(nrow * 144 + ks * 32 + (((lane >> 3) & 1) << 4)));
            }
#pragma unroll
            for (int g = 0; g < 2; g++) {
                mma_f16(sc[2 * g + 0], ah, &bk[g][0]);
                mma_f16(sc[2 * g + 1], ah, &bk[g][2]);
                mma_f16(sc[2 * g + 0], al, &bk[g][0]);
                mma_f16(sc[2 * g + 1], al, &bk[g][2]);
            }
        }

        // ---- biased exp + pack P fp16 ----
        uint32_t phi[2][4];
#pragma unroll
        for (int nt = 0; nt < 4; nt++)
#pragma unroll
            for (int e = 0; e < 4; e++) {
                float p = ex2f(sc[nt][e] * CEXP - EBIAS);
                sc[nt][e] = p;
                rs[e >> 1] += p;
            }
#pragma unroll
        for (int kt = 0; kt < 2; kt++) {
            phi[kt][0] = pack_f16(sc[2 * kt][0], sc[2 * kt][1]);
            phi[kt][1] = pack_f16(sc[2 * kt][2], sc[2 * kt][3]);
            phi[kt][2] = pack_f16(sc[2 * kt + 1][0], sc[2 * kt + 1][1]);
            phi[kt][3] = pack_f16(sc[2 * kt + 1][2], sc[2 * kt + 1][3]);
        }

        // ---- PV: single fp16 ----
#pragma unroll
        for (int kt = 0; kt < 2; kt++) {
            uint32_t vh[4][4];
#pragma unroll
            for (int g = 0; g < 4; g++) {
                int keyrow = wnk + kt * 16 + (lane & 7) + (((lane >> 3) & 1) << 3);
                ldsm_x4_t(vh[g], bufb + 9216
                          + (uint32_t)(keyrow * 144 + g * 32 + ((lane >> 4) << 4)));
            }
#pragma unroll
            for (int g = 0; g < 4; g++) {
                mma_f16(outacc[2 * g + 0], phi[kt], &vh[g][0]);
                mma_f16(outacc[2 * g + 1], phi[kt], &vh[g][2]);
            }
        }
        __syncthreads();
    }

    // ---- combine warp pairs, normalize, store fp16 ----
#pragma unroll
    for (int hf = 0; hf < 2; hf++) {
        rs[hf] += __shfl_xor_sync(0xffffffffu, rs[hf], 1);
        rs[hf] += __shfl_xor_sync(0xffffffffu, rs[hf], 2);
    }
    if ((lane & 3) == 0) {
#pragma unroll
        for (int hf = 0; hf < 2; hf++)
            rs2[(wm + (lane >> 2) + hf * 8) * 2 + (wid & 1)] = rs[hf];
    }
    if (wid & 1) {
#pragma unroll
        for (int nt = 0; nt < 8; nt++)
#pragma unroll
            for (int e = 0; e < 4; e++) {
                int row = wm + (lane >> 2) + (e >> 1) * 8;
                int col = nt * 8 + ((lane & 3) << 1) + (e & 1);
                outcmb[row * 66 + col] = outacc[nt][e];
            }
    }
    __syncthreads();
    if (!(wid & 1)) {
        int r0 = wm + (lane >> 2);
#pragma unroll
        for (int hf = 0; hf < 2; hf++) {
            int row = r0 + hf * 8;
            float inv = 1.f / (rs2[row * 2] + rs2[row * 2 + 1]);
            size_t grow = ((rowbase + q0 + row) << 10) + hoff;
#pragma unroll
            for (int nt = 0; nt < 8; nt++) {
                int col = nt * 8 + ((lane & 3) << 1);
                float v0 = (outacc[nt][hf * 2 + 0] + outcmb[row * 66 + col]) * inv;
                float v1 = (outacc[nt][hf * 2 + 1] + outcmb[row * 66 + col + 1]) * inv;
                *(uint32_t*)&Of[grow + col] = pack_f16(v0, v1);
            }
        }
    }
}

// ===========================================================================
// Launch
// ===========================================================================
extern "C" void kernel_launch(void* const* d_in, const int* in_sizes, int n_in,
                              void* d_out, int out_size) {
    const float* q    = (const float*)d_in[0];
    const float* k    = (const float*)d_in[1];
    const float* v    = (const float*)d_in[2];
    const float* wq_w = (const float*)d_in[3];
    const float* wq_b = (const float*)d_in[4];
    const float* wk_w = (const float*)d_in[5];
    const float* wk_b = (const float*)d_in[6];
    const float* wv_w = (const float*)d_in[7];
    const float* wv_b = (const float*)d_in[8];
    const float* wc_w = (const float*)d_in[9];
    const float* wc_b = (const float*)d_in[10];

    __nv_bfloat16 *pHi, *pLo, *pWq, *pWk;
    __half *pVact, *pQfh, *pQfl, *pKf, *pVf, *pAOf, *pWvf, *pWcf;
    float *pbq, *pbk, *pbv, *pbc;
    cudaGetSymbolAddress((void**)&pHi, g_hi);
    cudaGetSymbolAddress((void**)&pLo, g_lo);
    cudaGetSymbolAddress((void**)&pVact, g_vact);
    cudaGetSymbolAddress((void**)&pQfh, g_qfh);
    cudaGetSymbolAddress((void**)&pQfl, g_qfl);
    cudaGetSymbolAddress((void**)&pKf, g_kf);
    cudaGetSymbolAddress((void**)&pVf, g_vf);
    cudaGetSymbolAddress((void**)&pAOf, g_aof);
    cudaGetSymbolAddress((void**)&pWq, g_Wqc);
    cudaGetSymbolAddress((void**)&pWk, g_Wkc);
    cudaGetSymbolAddress((void**)&pWvf, g_Wvf);
    cudaGetSymbolAddress((void**)&pWcf, g_Wcf);
    cudaGetSymbolAddress((void**)&pbq, g_bq);
    cudaGetSymbolAddress((void**)&pbk, g_bk);
    cudaGetSymbolAddress((void**)&pbv, g_bv);
    cudaGetSymbolAddress((void**)&pbc, g_bc);

    const int TSLOT = PADROWS * DMODEL;

    cudaFuncSetAttribute(gemm_hmma_kernel, cudaFuncAttributeMaxDynamicSharedMemorySize, GEMM_SMEM);
    cudaFuncSetAttribute(attn_hmma_kernel, cudaFuncAttributeMaxDynamicSharedMemorySize, AT_SMEM);

    // 1) fused activation split
    SArgs sa;
    sa.X[0] = q; sa.X[1] = k; sa.X[2] = v;
    for (int t = 0; t < 2; t++) { sa.hi[t] = pHi + t * TSLOT; sa.lo[t] = pLo + t * TSLOT; }
    sa.vf = pVact;
    split_act_all<<<dim3(1, SPAD, 6), 256>>>(sa);

    // 2) fused weight transforms
    WArgs wa;
    wa.w[0] = wq_w; wa.w[1] = wk_w; wa.w[2] = wv_w; wa.w[3] = wc_w;
    wa.b[0] = wq_b; wa.b[1] = wk_b; wa.b[2] = wv_b; wa.b[3] = wc_b;
    wa.out[0] = pWq; wa.out[1] = pWk; wa.out[2] = pWvf; wa.out[3] = pWcf;
    wa.bP[0] = pbq; wa.bP[1] = pbk; wa.bP[2] = pbv; wa.bP[3] = pbc;
    wa.KS[0] = 3; wa.KS[1] = 3; wa.KS[2] = 1; wa.KS[3] = 1;
    wa.perm[0] = 1; wa.perm[1] = 1; wa.perm[2] = 1; wa.perm[3] = 0;
    wa.f16[0] = 0; wa.f16[1] = 0; wa.f16[2] = 1; wa.f16[3] = 1;
    transform_w_all<<<dim3(DMODEL, 4), 256>>>(wa);

    // 3) fused q/k/v projections:
    //    q: 3-term bf16 -> split fp16; k: 3-term bf16 -> single fp16; v: fp16 -> fp16
    GArgs gq = {};
    gq.Ah[0] = pHi + 0 * TSLOT; gq.Al[0] = pLo + 0 * TSLOT;
    gq.Ah[1] = pHi + 1 * TSLOT; gq.Al[1] = pLo + 1 * TSLOT;
    gq.Ah[2] = pVact;           gq.Al[2] = nullptr;
    gq.Ch[0] = pQfh; gq.Cl[0] = pQfl;
    gq.Ch[1] = pKf;  gq.Cl[1] = nullptr;
    gq.Ch[2] = pVf;  gq.Cl[2] = nullptr;
    gq.Bw[0] = pWq; gq.Bw[1] = pWk; gq.Bw[2] = pWvf;
    gq.bias[0] = pbq; gq.bias[1] = pbk; gq.bias[2] = pbv;
    gq.Cf = nullptr;
    gq.KS[0] = 3; gq.KS[1] = 3; gq.KS[2] = 1;
    gq.outMode[0] = 0; gq.outMode[1] = 1; gq.outMode[2] = 1;
    gq.f16mode[0] = 0; gq.f16mode[1] = 0; gq.f16mode[2] = 1;
    gemm_hmma_kernel<<<dim3(DMODEL / 128, (BATCH * SEQ) / 128, 3), 256, GEMM_SMEM>>>(gq);

    // 4) HMMA attention (QK 2-term fp16, PV fp16)
    dim3 gattn(SEQ / 64, NHEAD, BATCH);
    attn_hmma_kernel<<<gattn, 256, AT_SMEM>>>(pQfh, pQfl, pKf, pVf, pAOf);

    // 5) output linear -> d_out (fp32 out, fp16 single)
    GArgs gc = {};
    gc.Ah[0] = pAOf;
    gc.Bw[0] = pWcf; gc.bias[0] = pbc;
    gc.Cf = (float*)d_out;
    gc.KS[0] = 1;
    gc.outMode[0] = 2;
    gc.f16mode[0] = 1;
    gemm_hmma_kernel<<<dim3(DMODEL / 128, (BATCH * SEQ) / 128, 1), 256, GEMM_SMEM>>>(gc);
}

// round 16
// speedup vs baseline: 1.9835x; 1.0310x over previous
#include <cuda_runtime.h>
#include <cuda_bf16.h>
#include <cuda_fp16.h>
#include <cstdint>
#include <cstddef>

#define BATCH 2
#define SEQ 2048
#define SPAD 2050
#define DMODEL 1024
#define NHEAD 16
#define PADROWS (BATCH * SPAD)

// ===========================================================================
// Scratch
// ===========================================================================
__device__ __nv_bfloat16 g_hi[2 * PADROWS * DMODEL];   // q,k act split hi
__device__ __nv_bfloat16 g_lo[2 * PADROWS * DMODEL];
__device__ __half        g_vact[PADROWS * DMODEL];     // v activation fp16
__device__ __half        g_qfh[PADROWS * DMODEL];      // projected q fp16 hi
__device__ __half        g_qfl[PADROWS * DMODEL];      // projected q fp16 lo
__device__ __half        g_kf[PADROWS * DMODEL];       // projected k fp16 single
__device__ __half        g_vf[PADROWS * DMODEL];       // projected v fp16
__device__ __half        g_aof[PADROWS * DMODEL];      // attention out fp16
__device__ __nv_bfloat16 g_Wqc[DMODEL * 6144];   // {Whi x3 taps, Wlo x3 taps}
__device__ __nv_bfloat16 g_Wkc[DMODEL * 6144];
__device__ __half        g_Wvf[DMODEL * 1024];   // fp16 single
__device__ __half        g_Wcf[DMODEL * 1024];
__device__ float g_bq[DMODEL], g_bk[DMODEL], g_bv[DMODEL], g_bc[DMODEL];

// ===========================================================================
// PTX helpers
// ===========================================================================
__device__ __forceinline__ uint32_t smem_to_u32(const void* p) {
    uint32_t a;
    asm("{ .reg .u64 t; cvta.to.shared.u64 t, %1; cvt.u32.u64 %0, t; }" : "=r"(a) : "l"(p));
    return a;
}
__device__ __forceinline__ void cp16(uint32_t dst, const void* src) {
    asm volatile("cp.async.cg.shared.global [%0], [%1], 16;" :: "r"(dst), "l"(src));
}
__device__ __forceinline__ void ldsm_x4(uint32_t* r, uint32_t addr) {
    asm volatile("ldmatrix.sync.aligned.m8n8.x4.shared.b16 {%0,%1,%2,%3}, [%4];"
        : "=r"(r[0]), "=r"(r[1]), "=r"(r[2]), "=r"(r[3]) : "r"(addr));
}
__device__ __forceinline__ void ldsm_x4_t(uint32_t* r, uint32_t addr) {
    asm volatile("ldmatrix.sync.aligned.m8n8.x4.trans.shared.b16 {%0,%1,%2,%3}, [%4];"
        : "=r"(r[0]), "=r"(r[1]), "=r"(r[2]), "=r"(r[3]) : "r"(addr));
}
__device__ __forceinline__ void mma_bf16(float* d, const uint32_t* a, const uint32_t* b) {
    asm volatile(
        "mma.sync.aligned.m16n8k16.row.col.f32.bf16.bf16.f32 "
        "{%0,%1,%2,%3}, {%4,%5,%6,%7}, {%8,%9}, {%0,%1,%2,%3};"
        : "+f"(d[0]), "+f"(d[1]), "+f"(d[2]), "+f"(d[3])
        : "r"(a[0]), "r"(a[1]), "r"(a[2]), "r"(a[3]), "r"(b[0]), "r"(b[1]));
}
__device__ __forceinline__ void mma_f16(float* d, const uint32_t* a, const uint32_t* b) {
    asm volatile(
        "mma.sync.aligned.m16n8k16.row.col.f32.f16.f16.f32 "
        "{%0,%1,%2,%3}, {%4,%5,%6,%7}, {%8,%9}, {%0,%1,%2,%3};"
        : "+f"(d[0]), "+f"(d[1]), "+f"(d[2]), "+f"(d[3])
        : "r"(a[0]), "r"(a[1]), "r"(a[2]), "r"(a[3]), "r"(b[0]), "r"(b[1]));
}
__device__ __forceinline__ uint32_t pack_bf16(float lo, float hi) {
    uint32_t r; asm("cvt.rn.bf16x2.f32 %0, %1, %2;" : "=r"(r) : "f"(hi), "f"(lo)); return r;
}
__device__ __forceinline__ uint32_t pack_f16(float lo, float hi) {
    uint32_t r; asm("cvt.rn.f16x2.f32 %0, %1, %2;" : "=r"(r) : "f"(hi), "f"(lo)); return r;
}
__device__ __forceinline__ float f_low(uint32_t r)  { return __uint_as_float(r << 16); }
__device__ __forceinline__ float f_high(uint32_t r) { return __uint_as_float(r & 0xffff0000u); }
__device__ __forceinline__ float ex2f(float x) {
    float r; asm("ex2.approx.f32 %0, %1;" : "=f"(r) : "f"(x)); return r;
}
__device__ __forceinline__ void split_pair(float v0, float v1, uint32_t& h2, uint32_t& l2) {
    h2 = pack_bf16(v0, v1);
    l2 = pack_bf16(v0 - f_low(h2), v1 - f_high(h2));
}
__device__ __forceinline__ void split_pair_f16(float v0, float v1, uint32_t& h2, uint32_t& l2) {
    h2 = pack_f16(v0, v1);
    __half2 p = *(__half2*)&h2;
    l2 = pack_f16(v0 - __low2float(p), v1 - __high2float(p));
}

// ===========================================================================
// Fused prep: q,k -> bf16 hi/lo; v -> fp16. grid (1, 513, 6), 4 rows/block
// ===========================================================================
struct SArgs {
    const float* X[3];
    __nv_bfloat16* hi[2]; __nv_bfloat16* lo[2];
    __half* vf;
};

__global__ void split_act_all(SArgs sa) {
    int z = blockIdx.z;
    int t = z >> 1, b = z & 1;
    int c = threadIdx.x << 2;
#pragma unroll
    for (int ry = 0; ry < 4; ry++) {
        int y = (blockIdx.y << 2) + ry;
        if (y >= SPAD) break;
        float4 v = make_float4(0.f, 0.f, 0.f, 0.f);
        if (y >= 1 && y <= SEQ)
            v = *(const float4*)&sa.X[t][(((size_t)b * SEQ + (y - 1)) << 10) + c];
        size_t o = (((size_t)b * SPAD + y) << 10) + c;
        if (t < 2) {
            uint32_t h0, l0, h1, l1;
            split_pair(v.x, v.y, h0, l0);
            split_pair(v.z, v.w, h1, l1);
            *(uint2*)&sa.hi[t][o] = make_uint2(h0, h1);
            *(uint2*)&sa.lo[t][o] = make_uint2(l0, l1);
        } else {
            *(uint2*)&sa.vf[o] = make_uint2(pack_f16(v.x, v.y), pack_f16(v.z, v.w));
        }
    }
}

// ===========================================================================
// Fused prep: weight transforms. grid (1024, 4).
// ===========================================================================
struct WArgs {
    const float* w[4]; const float* b[4];
    void* out[4]; float* bP[4];
    int KS[4]; int perm[4]; int f16[4];
};

__global__ void transform_w_all(WArgs wa) {
    int ws = blockIdx.y;
    int c = blockIdx.x;
    int i = threadIdx.x << 2;
    int KS = wa.KS[ws];
    int o = wa.perm[ws] ? ((c & 63) * 16 + (c >> 6)) : c;
    const float* src = wa.w[ws] + ((size_t)o * 1024 + i) * KS;
    if (wa.f16[ws]) {
        __half* Wf = (__half*)wa.out[ws];
        for (int tap = 0; tap < KS; tap++) {
            float v0 = src[0 * KS + tap], v1 = src[1 * KS + tap];
            float v2 = src[2 * KS + tap], v3 = src[3 * KS + tap];
            *(uint2*)&Wf[(size_t)c * (KS << 10) + ((size_t)tap << 10) + i] =
                make_uint2(pack_f16(v0, v1), pack_f16(v2, v3));
        }
    } else {
        __nv_bfloat16* Wcat = (__nv_bfloat16*)wa.out[ws];
        const int W2 = (KS << 1) << 10;
        for (int tap = 0; tap < KS; tap++) {
            float v0 = src[0 * KS + tap], v1 = src[1 * KS + tap];
            float v2 = src[2 * KS + tap], v3 = src[3 * KS + tap];
            uint32_t h0, l0, h1, l1;
            split_pair(v0, v1, h0, l0);
            split_pair(v2, v3, h1, l1);
            *(uint2*)&Wcat[(size_t)c * W2 + ((size_t)tap << 10) + i] = make_uint2(h0, h1);
            *(uint2*)&Wcat[(size_t)c * W2 + ((size_t)(KS + tap) << 10) + i] = make_uint2(l0, l1);
        }
    }
    if (threadIdx.x == 0) wa.bP[ws][c] = wa.b[ws][o];
}

// ===========================================================================
// HMMA conv-GEMM (unchanged — passing R15). BM=128, BN=128, 2 CTAs/SM.
// ===========================================================================
#define G4_AMAT 18720
#define G4_ABUF (2 * G4_AMAT)
#define G4_AREG (2 * G4_ABUF)
#define G4_BTILE 18432
#define GEMM_SMEM (G4_AREG + 2 * G4_BTILE)

struct GArgs {
    const void* Ah[3]; const __nv_bfloat16* Al[3];
    const void* Bw[3]; const float* bias[3];
    void* Ch[3]; void* Cl[3];
    float* Cf;
    int KS[3];
    int outMode[3];
    int f16mode[3];
};

__global__ void __launch_bounds__(256, 2) gemm_hmma_kernel(GArgs ga)
{
    extern __shared__ __align__(128) char smem[];
    const uint32_t sb = smem_to_u32(smem);
    const int tid = threadIdx.x, wid = tid >> 5, lane = tid & 31;
    const int z = blockIdx.z;
    const char* __restrict__ Ahi = (const char*)ga.Ah[z];
    const __nv_bfloat16* __restrict__ Alo = ga.Al[z];
    const char* __restrict__ Bw  = (const char*)ga.Bw[z];
    const float* __restrict__ bP = ga.bias[z];
    const int KS = ga.KS[z];
    const int f16 = ga.f16mode[z];

    const int row0 = blockIdx.y << 7;
    const int col0 = blockIdx.x << 7;
    const int bb = row0 >> 11;
    const size_t base = (size_t)bb * SPAD + (row0 & 2047);
    const int NSEG = f16 ? KS : (KS << 1);
    const int Kp = NSEG << 10;
    const int J = NSEG << 4;
    const int tapAdd = (KS == 1) ? 1 : 0;
    const int wm = (wid >> 1) << 5;
    const int wn = (wid & 1) << 6;

    auto load_A = [&](int ch) {
        uint32_t dst = sb + (uint32_t)(ch & 1) * G4_ABUF;
        int c0 = ch << 6;
        const int nit = f16 ? 1040 : 2080;
#pragma unroll
        for (int l = 0; l < 9; l++) {
            int idx = tid + (l << 8);
            if (idx < nit) {
                int mat = 0;
                if (idx >= 1040) { idx -= 1040; mat = 1; }
                int r = idx >> 3, jc = idx & 7;
                const char* src = mat
                    ? (const char*)(Alo + (((base + r) << 10) + c0 + (jc << 3)))
                    : (Ahi + ((((base + r) << 10) + c0 + (jc << 3)) << 1));
                cp16(dst + (uint32_t)(mat * G4_AMAT + r * 144 + (jc << 4)), src);
            }
        }
    };
    auto load_B = [&](int j, int s, int ch) {
        uint32_t dst = sb + G4_AREG + (uint32_t)(j & 1) * G4_BTILE;
        size_t k0 = ((size_t)s << 10) + (ch << 6);
#pragma unroll
        for (int l = 0; l < 4; l++) {
            int idx = tid + (l << 8);
            int r = idx >> 3, jc = idx & 7;
            cp16(dst + (uint32_t)(r * 144 + (jc << 4)),
                 Bw + (((size_t)(col0 + r) * Kp + k0 + (jc << 3)) << 1));
        }
    };

    float acc[2][8][4];
#pragma unroll
    for (int mt = 0; mt < 2; mt++)
#pragma unroll
        for (int nt = 0; nt < 8; nt++)
#pragma unroll
            for (int e = 0; e < 4; e++) acc[mt][nt][e] = 0.f;

    load_A(0);
    load_B(0, 0, 0);
    asm volatile("cp.async.commit_group;");

    int s = 0, ch = 0;
    for (int j = 0; j < J; j++) {
        if (s == 0 && ch + 1 < 16) load_A(ch + 1);
        if (j + 1 < J) {
            int s2 = s + 1, ch2 = ch;
            if (s2 == NSEG) { s2 = 0; ch2++; }
            load_B(j + 1, s2, ch2);
            asm volatile("cp.async.commit_group;");
            asm volatile("cp.async.wait_group 1;");
        } else {
            asm volatile("cp.async.commit_group;");
            asm volatile("cp.async.wait_group 0;");
        }
        __syncthreads();

        const uint32_t AsmHi = sb + (uint32_t)(ch & 1) * G4_ABUF;
        const uint32_t AsmLo = AsmHi + G4_AMAT;
        const uint32_t Bsm = sb + G4_AREG + (uint32_t)(j & 1) * G4_BTILE;

        if (f16) {
            const int tap = s + tapAdd;
#pragma unroll
            for (int kk = 0; kk < 64; kk += 16) {
                uint32_t b[4][4], a[2][4];
#pragma unroll
                for (int g = 0; g < 4; g++) {
                    int nrow = wn + g * 16 + (lane & 7) + ((lane >> 4) << 3);
                    ldsm_x4(b[g], Bsm + (uint32_t)(nrow * 144 + (kk + (((lane >> 3) & 1) << 3)) * 2));
                }
#pragma unroll
                for (int mt = 0; mt < 2; mt++)
                    ldsm_x4(a[mt], AsmHi + (uint32_t)((wm + tap + mt * 16 + (lane & 15)) * 144
                            + ((lane >> 4) << 4) + kk * 2));
#pragma unroll
                for (int mt = 0; mt < 2; mt++)
#pragma unroll
                    for (int g = 0; g < 4; g++) {
                        mma_f16(acc[mt][2 * g + 0], a[mt], &b[g][0]);
                        mma_f16(acc[mt][2 * g + 1], a[mt], &b[g][2]);
                    }
            }
        } else {
            const int tap = (s < KS ? s : s - KS) + tapAdd;
            const bool doLo = (s < KS);
#pragma unroll
            for (int kk = 0; kk < 64; kk += 16) {
                uint32_t b[4][4], a[2][4];
#pragma unroll
                for (int g = 0; g < 4; g++) {
                    int nrow = wn + g * 16 + (lane & 7) + ((lane >> 4) << 3);
                    ldsm_x4(b[g], Bsm + (uint32_t)(nrow * 144 + (kk + (((lane >> 3) & 1) << 3)) * 2));
                }
#pragma unroll
                for (int mt = 0; mt < 2; mt++)
                    ldsm_x4(a[mt], AsmHi + (uint32_t)((wm + tap + mt * 16 + (lane & 15)) * 144
                            + ((lane >> 4) << 4) + kk * 2));
#pragma unroll
                for (int mt = 0; mt < 2; mt++)
#pragma unroll
                    for (int g = 0; g < 4; g++) {
                        mma_bf16(acc[mt][2 * g + 0], a[mt], &b[g][0]);
                        mma_bf16(acc[mt][2 * g + 1], a[mt], &b[g][2]);
                    }
                if (doLo) {
#pragma unroll
                    for (int mt = 0; mt < 2; mt++)
                        ldsm_x4(a[mt], AsmLo + (uint32_t)((wm + tap + mt * 16 + (lane & 15)) * 144
                                + ((lane >> 4) << 4) + kk * 2));
#pragma unroll
                    for (int mt = 0; mt < 2; mt++)
#pragma unroll
                        for (int g = 0; g < 4; g++) {
                            mma_bf16(acc[mt][2 * g + 0], a[mt], &b[g][0]);
                            mma_bf16(acc[mt][2 * g + 1], a[mt], &b[g][2]);
                        }
                }
            }
        }
        __syncthreads();
        if (++s == NSEG) { s = 0; ch++; }
    }

    const int om = ga.outMode[z];
    if (om == 0) {
        __half* __restrict__ Chi = (__half*)ga.Ch[z];
        __half* __restrict__ Clo = (__half*)ga.Cl[z];
        const int prow0 = bb * SPAD + (row0 & 2047) + 1;
#pragma unroll
        for (int mt = 0; mt < 2; mt++) {
            int rl = wm + mt * 16 + (lane >> 2);
#pragma unroll
            for (int nt = 0; nt < 8; nt++) {
                int c = col0 + wn + nt * 8 + ((lane & 3) << 1);
                float2 bv = *(const float2*)&bP[c];
                uint32_t h2, l2;
                split_pair_f16(acc[mt][nt][0] + bv.x, acc[mt][nt][1] + bv.y, h2, l2);
                size_t o0 = ((size_t)(prow0 + rl) << 10) + c;
                *(uint32_t*)&Chi[o0] = h2;
                *(uint32_t*)&Clo[o0] = l2;
                split_pair_f16(acc[mt][nt][2] + bv.x, acc[mt][nt][3] + bv.y, h2, l2);
                size_t o1 = ((size_t)(prow0 + rl + 8) << 10) + c;
                *(uint32_t*)&Chi[o1] = h2;
                *(uint32_t*)&Clo[o1] = l2;
            }
        }
    } else if (om == 1) {
        __half* __restrict__ Cv = (__half*)ga.Ch[z];
        const int prow0 = bb * SPAD + (row0 & 2047) + 1;
#pragma unroll
        for (int mt = 0; mt < 2; mt++) {
            int rl = wm + mt * 16 + (lane >> 2);
#pragma unroll
            for (int nt = 0; nt < 8; nt++) {
                int c = col0 + wn + nt * 8 + ((lane & 3) << 1);
                float2 bv = *(const float2*)&bP[c];
                uint32_t p0 = pack_f16(acc[mt][nt][0] + bv.x, acc[mt][nt][1] + bv.y);
                uint32_t p1 = pack_f16(acc[mt][nt][2] + bv.x, acc[mt][nt][3] + bv.y);
                *(uint32_t*)&Cv[((size_t)(prow0 + rl) << 10) + c] = p0;
                *(uint32_t*)&Cv[((size_t)(prow0 + rl + 8) << 10) + c] = p1;
            }
        }
    } else {
        float* __restrict__ Cf = ga.Cf;
#pragma unroll
        for (int mt = 0; mt < 2; mt++) {
            int r = row0 + wm + mt * 16 + (lane >> 2);
#pragma unroll
            for (int nt = 0; nt < 8; nt++) {
                int c = col0 + wn + nt * 8 + ((lane & 3) << 1);
                float2 bv = *(const float2*)&bP[c];
                *(float2*)&Cf[(size_t)r * 1024 + c] =
                    make_float2(acc[mt][nt][0] + bv.x, acc[mt][nt][1] + bv.y);
                *(float2*)&Cf[(size_t)(r + 8) * 1024 + c] =
                    make_float2(acc[mt][nt][2] + bv.x, acc[mt][nt][3] + bv.y);
            }
        }
    }
}

// ===========================================================================
// HMMA flash attention: QK 2-term fp16, PV single fp16.
// 64 q-rows/block; 128-key KV chunks processed as two 64-key passes
// (halved syncs, doubled cp.async batches). Arithmetic identical to R15.
// smem: Qh/Ql 18432 + 2 x (K 18432 + V 18432) + 1024 = 93184. 2 CTAs/SM.
// ===========================================================================
#define AT_QREG 18432
#define AT_KVBUF 36864
#define AT_SMEM (AT_QREG + 2 * AT_KVBUF + 1024)   // 93184

__global__ void __launch_bounds__(256, 2) attn_hmma_kernel(
    const __half* __restrict__ Qh, const __half* __restrict__ Ql,
    const __half* __restrict__ Kf, const __half* __restrict__ Vf,
    __half* __restrict__ Of)
{
    extern __shared__ __align__(128) char smem[];
    const uint32_t sb = smem_to_u32(smem);
    const uint32_t sKV = sb + AT_QREG;
    float* rs2 = (float*)(smem + AT_QREG + 2 * AT_KVBUF);
    float* outcmb = (float*)(smem + AT_QREG);

    const int tid = threadIdx.x, wid = tid >> 5, lane = tid & 31;
    const int wm = (wid >> 1) << 4;
    const int wnk = (wid & 1) << 5;
    const int q0 = blockIdx.x << 6;
    const int h = blockIdx.y, b = blockIdx.z;
    const size_t hoff = (size_t)h * 64;
    const size_t rowbase = (size_t)b * SPAD + 1;

#pragma unroll
    for (int l = 0; l < 4; l++) {
        int mat = l >> 1;
        int r = (tid >> 3) + ((l & 1) << 5);
        int j = tid & 7;
        const __half* src = (mat ? Ql : Qh) + (((rowbase + q0 + r) << 10) + hoff + (j << 3));
        cp16(sb + (uint32_t)(mat * 9216 + r * 144 + j * 16), src);
    }
    asm volatile("cp.async.commit_group;");

    // one chunk = 128 keys: K rows [0,128) at offset 0, V rows at 18432
    auto loadKV = [&](int c) {
        uint32_t dstb = sKV + (uint32_t)(c & 1) * AT_KVBUF;
        size_t krow = rowbase + ((size_t)c << 7);
#pragma unroll
        for (int l = 0; l < 8; l++) {
            int mat = l >> 2;                   // 0:K 1:V
            int r = (tid >> 3) + ((l & 3) << 5);
            int j = tid & 7;
            const __half* src = (mat ? Vf : Kf) + (((krow + r) << 10) + hoff + (j << 3));
            cp16(dstb + (uint32_t)(mat * 18432 + r * 144 + j * 16), src);
        }
    };
    loadKV(0);
    asm volatile("cp.async.commit_group;");

    float outacc[8][4];
    float rs[2] = {0.f, 0.f};
#pragma unroll
    for (int nt = 0; nt < 8; nt++)
#pragma unroll
        for (int e = 0; e < 4; e++) outacc[nt][e] = 0.f;

    const float CEXP = 1.4426950408889634f * 0.125f;
    const float EBIAS = 17.312340490667562f;

    for (int c = 0; c < 16; c++) {
        if (c + 1 < 16) {
            loadKV(c + 1);
            asm volatile("cp.async.commit_group;");
            asm volatile("cp.async.wait_group 1;");
        } else {
            asm volatile("cp.async.wait_group 0;");
        }
        __syncthreads();
        uint32_t bufb = sKV + (uint32_t)(c & 1) * AT_KVBUF;

#pragma unroll
        for (int half = 0; half < 2; half++) {
            const uint32_t kbase = bufb + (uint32_t)(half << 6) * 144;
            const uint32_t vbase = bufb + 18432 + (uint32_t)(half << 6) * 144;

            // ---- scores: 2-term fp16 (qh + ql) x k ----
            float sc[4][4];
#pragma unroll
            for (int nt = 0; nt < 4; nt++)
#pragma unroll
                for (int e = 0; e < 4; e++) sc[nt][e] = 0.f;

#pragma unroll
            for (int ks = 0; ks < 4; ks++) {
                uint32_t ah[4], al[4], bk[2][4];
                uint32_t qaddr = sb + (uint32_t)((wm + (lane & 15)) * 144
                                 + ((lane >> 4) << 4) + ks * 32);
                ldsm_x4(ah, qaddr);
                ldsm_x4(al, qaddr + 9216);
#pragma unroll
                for (int g = 0; g < 2; g++) {
                    int nrow = wnk + g * 16 + (lane & 7) + ((lane >> 4) << 3);
                    ldsm_x4(bk[g], kbase + (uint32_t)(nrow * 144 + ks * 32 + (((lane >> 3) & 1) << 4)));
                }
#pragma unroll
                for (int g = 0; g < 2; g++) {
                    mma_f16(sc[2 * g + 0], ah, &bk[g][0]);
                    mma_f16(sc[2 * g + 1], ah, &bk[g][2]);
                    mma_f16(sc[2 * g + 0], al, &bk[g][0]);
                    mma_f16(sc[2 * g + 1], al, &bk[g][2]);
                }
            }

            // ---- biased exp + pack P fp16 ----
            uint32_t phi[2][4];
#pragma unroll
            for (int nt = 0; nt < 4; nt++)
#pragma unroll
                for (int e = 0; e < 4; e++) {
                    float p = ex2f(sc[nt][e] * CEXP - EBIAS);
                    sc[nt][e] = p;
                    rs[e >> 1] += p;
                }
#pragma unroll
            for (int kt = 0; kt < 2; kt++) {
                phi[kt][0] = pack_f16(sc[2 * kt][0], sc[2 * kt][1]);
                phi[kt][1] = pack_f16(sc[2 * kt][2], sc[2 * kt][3]);
                phi[kt][2] = pack_f16(sc[2 * kt + 1][0], sc[2 * kt + 1][1]);
                phi[kt][3] = pack_f16(sc[2 * kt + 1][2], sc[2 * kt + 1][3]);
            }

            // ---- PV: single fp16 ----
#pragma unroll
            for (int kt = 0; kt < 2; kt++) {
                uint32_t vh[4][4];
#pragma unroll
                for (int g = 0; g < 4; g++) {
                    int keyrow = wnk + kt * 16 + (lane & 7) + (((lane >> 3) & 1) << 3);
                    ldsm_x4_t(vh[g], vbase + (uint32_t)(keyrow * 144 + g * 32 + ((lane >> 4) << 4)));
                }
#pragma unroll
                for (int g = 0; g < 4; g++) {
                    mma_f16(outacc[2 * g + 0], phi[kt], &vh[g][0]);
                    mma_f16(outacc[2 * g + 1], phi[kt], &vh[g][2]);
                }
            }
        }
        __syncthreads();
    }

    // ---- combine warp pairs, normalize, store fp16 ----
#pragma unroll
    for (int hf = 0; hf < 2; hf++) {
        rs[hf] += __shfl_xor_sync(0xffffffffu, rs[hf], 1);
        rs[hf] += __shfl_xor_sync(0xffffffffu, rs[hf], 2);
    }
    if ((lane & 3) == 0) {
#pragma unroll
        for (int hf = 0; hf < 2; hf++)
            rs2[(wm + (lane >> 2) + hf * 8) * 2 + (wid & 1)] = rs[hf];
    }
    if (wid & 1) {
#pragma unroll
        for (int nt = 0; nt < 8; nt++)
#pragma unroll
            for (int e = 0; e < 4; e++) {
                int row = wm + (lane >> 2) + (e >> 1) * 8;
                int col = nt * 8 + ((lane & 3) << 1) + (e & 1);
                outcmb[row * 66 + col] = outacc[nt][e];
            }
    }
    __syncthreads();
    if (!(wid & 1)) {
        int r0 = wm + (lane >> 2);
#pragma unroll
        for (int hf = 0; hf < 2; hf++) {
            int row = r0 + hf * 8;
            float inv = 1.f / (rs2[row * 2] + rs2[row * 2 + 1]);
            size_t grow = ((rowbase + q0 + row) << 10) + hoff;
#pragma unroll
            for (int nt = 0; nt < 8; nt++) {
                int col = nt * 8 + ((lane & 3) << 1);
                float v0 = (outacc[nt][hf * 2 + 0] + outcmb[row * 66 + col]) * inv;
                float v1 = (outacc[nt][hf * 2 + 1] + outcmb[row * 66 + col + 1]) * inv;
                *(uint32_t*)&Of[grow + col] = pack_f16(v0, v1);
            }
        }
    }
}

// ===========================================================================
// Launch
// ===========================================================================
extern "C" void kernel_launch(void* const* d_in, const int* in_sizes, int n_in,
                              void* d_out, int out_size) {
    const float* q    = (const float*)d_in[0];
    const float* k    = (const float*)d_in[1];
    const float* v    = (const float*)d_in[2];
    const float* wq_w = (const float*)d_in[3];
    const float* wq_b = (const float*)d_in[4];
    const float* wk_w = (const float*)d_in[5];
    const float* wk_b = (const float*)d_in[6];
    const float* wv_w = (const float*)d_in[7];
    const float* wv_b = (const float*)d_in[8];
    const float* wc_w = (const float*)d_in[9];
    const float* wc_b = (const float*)d_in[10];

    __nv_bfloat16 *pHi, *pLo, *pWq, *pWk;
    __half *pVact, *pQfh, *pQfl, *pKf, *pVf, *pAOf, *pWvf, *pWcf;
    float *pbq, *pbk, *pbv, *pbc;
    cudaGetSymbolAddress((void**)&pHi, g_hi);
    cudaGetSymbolAddress((void**)&pLo, g_lo);
    cudaGetSymbolAddress((void**)&pVact, g_vact);
    cudaGetSymbolAddress((void**)&pQfh, g_qfh);
    cudaGetSymbolAddress((void**)&pQfl, g_qfl);
    cudaGetSymbolAddress((void**)&pKf, g_kf);
    cudaGetSymbolAddress((void**)&pVf, g_vf);
    cudaGetSymbolAddress((void**)&pAOf, g_aof);
    cudaGetSymbolAddress((void**)&pWq, g_Wqc);
    cudaGetSymbolAddress((void**)&pWk, g_Wkc);
    cudaGetSymbolAddress((void**)&pWvf, g_Wvf);
    cudaGetSymbolAddress((void**)&pWcf, g_Wcf);
    cudaGetSymbolAddress((void**)&pbq, g_bq);
    cudaGetSymbolAddress((void**)&pbk, g_bk);
    cudaGetSymbolAddress((void**)&pbv, g_bv);
    cudaGetSymbolAddress((void**)&pbc, g_bc);

    const int TSLOT = PADROWS * DMODEL;

    cudaFuncSetAttribute(gemm_hmma_kernel, cudaFuncAttributeMaxDynamicSharedMemorySize, GEMM_SMEM);
    cudaFuncSetAttribute(attn_hmma_kernel, cudaFuncAttributeMaxDynamicSharedMemorySize, AT_SMEM);

    // 1) fused activation split (4 rows/block)
    SArgs sa;
    sa.X[0] = q; sa.X[1] = k; sa.X[2] = v;
    for (int t = 0; t < 2; t++) { sa.hi[t] = pHi + t * TSLOT; sa.lo[t] = pLo + t * TSLOT; }
    sa.vf = pVact;
    split_act_all<<<dim3(1, (SPAD + 3) / 4, 6), 256>>>(sa);

    // 2) fused weight transforms
    WArgs wa;
    wa.w[0] = wq_w; wa.w[1] = wk_w; wa.w[2] = wv_w; wa.w[3] = wc_w;
    wa.b[0] = wq_b; wa.b[1] = wk_b; wa.b[2] = wv_b; wa.b[3] = wc_b;
    wa.out[0] = pWq; wa.out[1] = pWk; wa.out[2] = pWvf; wa.out[3] = pWcf;
    wa.bP[0] = pbq; wa.bP[1] = pbk; wa.bP[2] = pbv; wa.bP[3] = pbc;
    wa.KS[0] = 3; wa.KS[1] = 3; wa.KS[2] = 1; wa.KS[3] = 1;
    wa.perm[0] = 1; wa.perm[1] = 1; wa.perm[2] = 1; wa.perm[3] = 0;
    wa.f16[0] = 0; wa.f16[1] = 0; wa.f16[2] = 1; wa.f16[3] = 1;
    transform_w_all<<<dim3(DMODEL, 4), 256>>>(wa);

    // 3) fused q/k/v projections
    GArgs gq = {};
    gq.Ah[0] = pHi + 0 * TSLOT; gq.Al[0] = pLo + 0 * TSLOT;
    gq.Ah[1] = pHi + 1 * TSLOT; gq.Al[1] = pLo + 1 * TSLOT;
    gq.Ah[2] = pVact;           gq.Al[2] = nullptr;
    gq.Ch[0] = pQfh; gq.Cl[0] = pQfl;
    gq.Ch[1] = pKf;  gq.Cl[1] = nullptr;
    gq.Ch[2] = pVf;  gq.Cl[2] = nullptr;
    gq.Bw[0] = pWq; gq.Bw[1] = pWk; gq.Bw[2] = pWvf;
    gq.bias[0] = pbq; gq.bias[1] = pbk; gq.bias[2] = pbv;
    gq.Cf = nullptr;
    gq.KS[0] = 3; gq.KS[1] = 3; gq.KS[2] = 1;
    gq.outMode[0] = 0; gq.outMode[1] = 1; gq.outMode[2] = 1;
    gq.f16mode[0] = 0; gq.f16mode[1] = 0; gq.f16mode[2] = 1;
    gemm_hmma_kernel<<<dim3(DMODEL / 128, (BATCH * SEQ) / 128, 3), 256, GEMM_SMEM>>>(gq);

    // 4) HMMA attention (128-key chunks, two passes)
    dim3 gattn(SEQ / 64, NHEAD, BATCH);
    attn_hmma_kernel<<<gattn, 256, AT_SMEM>>>(pQfh, pQfl, pKf, pVf, pAOf);

    // 5) output linear -> d_out
    GArgs gc = {};
    gc.Ah[0] = pAOf;
    gc.Bw[0] = pWcf; gc.bias[0] = pbc;
    gc.Cf = (float*)d_out;
    gc.KS[0] = 1;
    gc.outMode[0] = 2;
    gc.f16mode[0] = 1;
    gemm_hmma_kernel<<<dim3(DMODEL / 128, (BATCH * SEQ) / 128, 1), 256, GEMM_SMEM>>>(gc);
}